// round 1
// baseline (speedup 1.0000x reference)
#include <cuda_runtime.h>
#include <math.h>

#define NN 100000
#define EE 3200000
#define GG 64

// ---------------- scratch (static device allocations; allowed) ----------------
__device__ float g_q1[NN * 64];
__device__ float g_k1[NN * 64];
__device__ float g_v1[NN * 64];
__device__ float g_h [NN * 64];
__device__ float g_logits1[(size_t)EE * 4];
__device__ float g_m1 [NN * 4];
__device__ float g_den1[NN * 4];
__device__ float g_num1[NN * 64];

__device__ float g_q2[NN * 6];
__device__ float g_k2[NN * 6];
__device__ float g_v2[NN * 6];
__device__ float g_s2[NN * 6];
__device__ float g_logits2[EE];
__device__ float g_m2 [NN];
__device__ float g_den2[NN];
__device__ float g_num2[NN * 6];

__device__ float g_sums[GG * 6];
__device__ float g_cnt [GG];

// float atomic max via sign-split int/uint trick (handles -0.0 correctly)
__device__ __forceinline__ void atomicMaxFloat(float* addr, float value) {
    int vi = __float_as_int(value);
    if (vi >= 0) atomicMax((int*)addr, vi);
    else         atomicMin((unsigned int*)addr, (unsigned int)vi);
}

// ---------------- kernels ----------------

__global__ void k_init(int n) {
    int i = blockIdx.x * blockDim.x + threadIdx.x;
    if (i < n * 64) g_num1[i] = 0.f;
    if (i < n * 6)  g_num2[i] = 0.f;
    if (i < n * 4)  { g_m1[i] = -INFINITY; g_den1[i] = 0.f; }
    if (i < n)      { g_m2[i] = -INFINITY; g_den2[i] = 0.f; }
    if (i < GG * 6) g_sums[i] = 0.f;
    if (i < GG)     g_cnt[i]  = 0.f;
}

// q1/k1/v1 = x @ W + b  (x: [N,3], W: [3,64])
__global__ void k_gemm1(const float* __restrict__ x,
                        const float* __restrict__ Wq, const float* __restrict__ bq,
                        const float* __restrict__ Wk, const float* __restrict__ bk,
                        const float* __restrict__ Wv, const float* __restrict__ bv,
                        int n) {
    int idx = blockIdx.x * blockDim.x + threadIdx.x;
    if (idx >= n * 64) return;
    int node = idx >> 6, c = idx & 63;
    float x0 = __ldg(&x[node * 3 + 0]);
    float x1 = __ldg(&x[node * 3 + 1]);
    float x2 = __ldg(&x[node * 3 + 2]);
    g_q1[idx] = bq[c] + x0 * Wq[c] + x1 * Wq[64 + c] + x2 * Wq[128 + c];
    g_k1[idx] = bk[c] + x0 * Wk[c] + x1 * Wk[64 + c] + x2 * Wk[128 + c];
    g_v1[idx] = bv[c] + x0 * Wv[c] + x1 * Wv[64 + c] + x2 * Wv[128 + c];
}

// per (edge, head) attention logit, layer 1
__global__ void k_edge_logits1(const int* __restrict__ src, const int* __restrict__ dst,
                               int e_total) {
    int idx = blockIdx.x * blockDim.x + threadIdx.x;  // e*4 + h
    if (idx >= e_total * 4) return;
    int e = idx >> 2, h = idx & 3;
    int s = __ldg(&src[e]);
    int t = __ldg(&dst[e]);
    const float4* qp = reinterpret_cast<const float4*>(g_q1 + t * 64 + h * 16);
    const float4* kp = reinterpret_cast<const float4*>(g_k1 + s * 64 + h * 16);
    float acc = 0.f;
#pragma unroll
    for (int i = 0; i < 4; i++) {
        float4 q = qp[i], k = kp[i];
        acc += q.x * k.x + q.y * k.y + q.z * k.z + q.w * k.w;
    }
    float logit = acc * 0.25f;  // / sqrt(16)
    g_logits1[idx] = logit;
    atomicMaxFloat(&g_m1[t * 4 + h], logit);
}

// accumulate denom & numerator, layer 1
__global__ void k_edge_accum1(const int* __restrict__ src, const int* __restrict__ dst,
                              int e_total) {
    int idx = blockIdx.x * blockDim.x + threadIdx.x;  // e*4 + h
    if (idx >= e_total * 4) return;
    int e = idx >> 2, h = idx & 3;
    int s = __ldg(&src[e]);
    int t = __ldg(&dst[e]);
    float a = __expf(g_logits1[idx] - g_m1[t * 4 + h]);
    atomicAdd(&g_den1[t * 4 + h], a);
    const float4* vp = reinterpret_cast<const float4*>(g_v1 + s * 64 + h * 16);
    float* np = g_num1 + t * 64 + h * 16;
#pragma unroll
    for (int i = 0; i < 4; i++) {
        float4 v = vp[i];
        atomicAdd(np + 4 * i + 0, a * v.x);
        atomicAdd(np + 4 * i + 1, a * v.y);
        atomicAdd(np + 4 * i + 2, a * v.z);
        atomicAdd(np + 4 * i + 3, a * v.w);
    }
}

// h = relu(num/den + x @ Ws1 + bs1)
__global__ void k_final1(const float* __restrict__ x,
                         const float* __restrict__ Ws, const float* __restrict__ bs,
                         int n) {
    int idx = blockIdx.x * blockDim.x + threadIdx.x;
    if (idx >= n * 64) return;
    int node = idx >> 6, c = idx & 63, h = c >> 4;
    float val = g_num1[idx] / (g_den1[node * 4 + h] + 1e-16f);
    float x0 = __ldg(&x[node * 3 + 0]);
    float x1 = __ldg(&x[node * 3 + 1]);
    float x2 = __ldg(&x[node * 3 + 2]);
    val += bs[c] + x0 * Ws[c] + x1 * Ws[64 + c] + x2 * Ws[128 + c];
    g_h[idx] = fmaxf(val, 0.f);
}

// q2/k2/v2/s2 = h @ W + b  (h: [N,64], W: [64,6]); one 64-thread block per node
__global__ void k_gemm2(const float* __restrict__ Wq, const float* __restrict__ bq,
                        const float* __restrict__ Wk, const float* __restrict__ bk,
                        const float* __restrict__ Wv, const float* __restrict__ bv,
                        const float* __restrict__ Ws, const float* __restrict__ bs,
                        int n) {
    __shared__ float sh[64];
    int node = blockIdx.x;
    if (node >= n) return;
    sh[threadIdx.x] = g_h[node * 64 + threadIdx.x];
    __syncthreads();
    int j = threadIdx.x;
    if (j < 24) {
        int m = j / 6, c = j % 6;
        const float* W = (m == 0) ? Wq : (m == 1) ? Wk : (m == 2) ? Wv : Ws;
        const float* b = (m == 0) ? bq : (m == 1) ? bk : (m == 2) ? bv : bs;
        float acc = b[c];
#pragma unroll
        for (int k = 0; k < 64; k++) acc += sh[k] * W[k * 6 + c];
        float* O = (m == 0) ? g_q2 : (m == 1) ? g_k2 : (m == 2) ? g_v2 : g_s2;
        O[node * 6 + c] = acc;
    }
}

__global__ void k_edge_logits2(const int* __restrict__ src, const int* __restrict__ dst,
                               int e_total) {
    int e = blockIdx.x * blockDim.x + threadIdx.x;
    if (e >= e_total) return;
    int s = __ldg(&src[e]);
    int t = __ldg(&dst[e]);
    float acc = 0.f;
#pragma unroll
    for (int j = 0; j < 6; j++) acc += g_q2[t * 6 + j] * g_k2[s * 6 + j];
    float logit = acc * 0.4082482904638631f;  // 1/sqrt(6)
    g_logits2[e] = logit;
    atomicMaxFloat(&g_m2[t], logit);
}

__global__ void k_edge_accum2(const int* __restrict__ src, const int* __restrict__ dst,
                              int e_total) {
    int e = blockIdx.x * blockDim.x + threadIdx.x;
    if (e >= e_total) return;
    int s = __ldg(&src[e]);
    int t = __ldg(&dst[e]);
    float a = __expf(g_logits2[e] - g_m2[t]);
    atomicAdd(&g_den2[t], a);
#pragma unroll
    for (int j = 0; j < 6; j++)
        atomicAdd(&g_num2[t * 6 + j], a * g_v2[s * 6 + j]);
}

// finalize layer 2 + block-local pooling keyed by graph id (batch is sorted)
__global__ void k_final2_pool(const int* __restrict__ batch, int n) {
    __shared__ float ssum[GG * 6];
    __shared__ float scnt[GG];
    __shared__ int   sflag[GG];
    int tid = threadIdx.x;
    for (int i = tid; i < GG * 6; i += blockDim.x) ssum[i] = 0.f;
    for (int i = tid; i < GG; i += blockDim.x) { scnt[i] = 0.f; sflag[i] = 0; }
    __syncthreads();

    int node = blockIdx.x * blockDim.x + tid;
    if (node < n) {
        int g = __ldg(&batch[node]);
        float d = g_den2[node] + 1e-16f;
#pragma unroll
        for (int c = 0; c < 6; c++) {
            float v = g_num2[node * 6 + c] / d + g_s2[node * 6 + c];
            atomicAdd(&ssum[g * 6 + c], v);
        }
        atomicAdd(&scnt[g], 1.f);
        sflag[g] = 1;
    }
    __syncthreads();
    for (int g = tid; g < GG; g += blockDim.x) {
        if (sflag[g]) {
            atomicAdd(&g_cnt[g], scnt[g]);
#pragma unroll
            for (int c = 0; c < 6; c++)
                atomicAdd(&g_sums[g * 6 + c], ssum[g * 6 + c]);
        }
    }
}

// pooled mean + log_softmax -> d_out[G,6]
__global__ void k_out(float* __restrict__ out) {
    int g = threadIdx.x;
    if (g >= GG) return;
    float cnt = fmaxf(g_cnt[g], 1.f);
    float p[6];
    float m = -INFINITY;
#pragma unroll
    for (int c = 0; c < 6; c++) { p[c] = g_sums[g * 6 + c] / cnt; m = fmaxf(m, p[c]); }
    float s = 0.f;
#pragma unroll
    for (int c = 0; c < 6; c++) s += expf(p[c] - m);
    float lse = m + logf(s);
#pragma unroll
    for (int c = 0; c < 6; c++) out[g * 6 + c] = p[c] - lse;
}

// ---------------- launch ----------------
extern "C" void kernel_launch(void* const* d_in, const int* in_sizes, int n_in,
                              void* d_out, int out_size) {
    const float* x    = (const float*)d_in[0];
    const int*   ei   = (const int*)  d_in[1];
    const int*   batch= (const int*)  d_in[2];
    const float* Wq1  = (const float*)d_in[3];
    const float* bq1  = (const float*)d_in[4];
    const float* Wk1  = (const float*)d_in[5];
    const float* bk1  = (const float*)d_in[6];
    const float* Wv1  = (const float*)d_in[7];
    const float* bv1  = (const float*)d_in[8];
    const float* Ws1  = (const float*)d_in[9];
    const float* bs1  = (const float*)d_in[10];
    const float* Wq2  = (const float*)d_in[11];
    const float* bq2  = (const float*)d_in[12];
    const float* Wk2  = (const float*)d_in[13];
    const float* bk2  = (const float*)d_in[14];
    const float* Wv2  = (const float*)d_in[15];
    const float* bv2  = (const float*)d_in[16];
    const float* Ws2  = (const float*)d_in[17];
    const float* bs2  = (const float*)d_in[18];
    float* out = (float*)d_out;

    int N = in_sizes[0] / 3;
    int E = in_sizes[1] / 2;
    const int* src = ei;
    const int* dst = ei + E;

    const int B = 256;
    k_init<<<(N * 64 + B - 1) / B, B>>>(N);
    k_gemm1<<<(N * 64 + B - 1) / B, B>>>(x, Wq1, bq1, Wk1, bk1, Wv1, bv1, N);
    k_edge_logits1<<<(E * 4 + B - 1) / B, B>>>(src, dst, E);
    k_edge_accum1 <<<(E * 4 + B - 1) / B, B>>>(src, dst, E);
    k_final1<<<(N * 64 + B - 1) / B, B>>>(x, Ws1, bs1, N);
    k_gemm2<<<N, 64>>>(Wq2, bq2, Wk2, bk2, Wv2, bv2, Ws2, bs2, N);
    k_edge_logits2<<<(E + B - 1) / B, B>>>(src, dst, E);
    k_edge_accum2 <<<(E + B - 1) / B, B>>>(src, dst, E);
    k_final2_pool<<<(N + B - 1) / B, B>>>(batch, N);
    k_out<<<1, 64>>>(out);
}

// round 2
// speedup vs baseline: 2.2875x; 2.2875x over previous
#include <cuda_runtime.h>
#include <math.h>

#define NN 100000
#define EE 3200000
#define GG 64

// ---------------- static device scratch ----------------
__device__ float g_q1[NN * 64];
__device__ float g_k1[NN * 64];
__device__ float g_v1[NN * 64];
__device__ float g_h [NN * 64];

__device__ float g_q2[NN * 6];
__device__ float g_k2[NN * 6];
__device__ float g_v2[NN * 6];
__device__ float g_s2[NN * 6];
__device__ float g_o2[NN * 6];

__device__ int g_deg   [NN];
__device__ int g_rowptr[NN + 1];
__device__ int g_cursor[NN];
__device__ int g_csrsrc[EE];

__device__ float g_sums[GG * 6];
__device__ float g_cnt [GG];

// ---------------- CSR build ----------------

__global__ void k_zero(int n) {
    int i = blockIdx.x * blockDim.x + threadIdx.x;
    if (i < n) g_deg[i] = 0;
    if (i < GG * 6) g_sums[i] = 0.f;
    if (i < GG) g_cnt[i] = 0.f;
}

__global__ void k_hist(const int* __restrict__ dst, int e) {
    int i = blockIdx.x * blockDim.x + threadIdx.x;
    if (i < e) atomicAdd(&g_deg[dst[i]], 1);
}

// single-block exclusive scan over g_deg -> g_rowptr, g_cursor
__global__ void k_scan(int n, int e) {
    __shared__ int ssum[1024];
    int tid = threadIdx.x;
    int chunk = (n + 1023) / 1024;
    int lo = tid * chunk; if (lo > n) lo = n;
    int hi = lo + chunk;  if (hi > n) hi = n;
    int s = 0;
    for (int i = lo; i < hi; i++) s += g_deg[i];
    ssum[tid] = s;
    __syncthreads();
    for (int off = 1; off < 1024; off <<= 1) {
        int v = (tid >= off) ? ssum[tid - off] : 0;
        __syncthreads();
        ssum[tid] += v;
        __syncthreads();
    }
    int run = ssum[tid] - s;  // exclusive prefix of this chunk
    for (int i = lo; i < hi; i++) {
        int d = g_deg[i];
        g_rowptr[i] = run;
        g_cursor[i] = run;
        run += d;
    }
    if (tid == 0) g_rowptr[n] = e;
}

__global__ void k_scatter(const int* __restrict__ src, const int* __restrict__ dst, int e) {
    int i = blockIdx.x * blockDim.x + threadIdx.x;
    if (i >= e) return;
    int p = atomicAdd(&g_cursor[dst[i]], 1);
    g_csrsrc[p] = src[i];
}

// ---------------- layer 1 ----------------

// q1/k1/v1 = x @ W + b  (x: [N,3], W: [3,64])
__global__ void k_gemm1(const float* __restrict__ x,
                        const float* __restrict__ Wq, const float* __restrict__ bq,
                        const float* __restrict__ Wk, const float* __restrict__ bk,
                        const float* __restrict__ Wv, const float* __restrict__ bv,
                        int n) {
    int idx = blockIdx.x * blockDim.x + threadIdx.x;
    if (idx >= n * 64) return;
    int node = idx >> 6, c = idx & 63;
    float x0 = __ldg(&x[node * 3 + 0]);
    float x1 = __ldg(&x[node * 3 + 1]);
    float x2 = __ldg(&x[node * 3 + 2]);
    g_q1[idx] = bq[c] + x0 * Wq[c] + x1 * Wq[64 + c] + x2 * Wq[128 + c];
    g_k1[idx] = bk[c] + x0 * Wk[c] + x1 * Wk[64 + c] + x2 * Wk[128 + c];
    g_v1[idx] = bv[c] + x0 * Wv[c] + x1 * Wv[64 + c] + x2 * Wv[128 + c];
}

// fused attention layer 1: warp per node, online softmax, + skip + relu -> g_h
__global__ void k_attn1(const float* __restrict__ x,
                        const float* __restrict__ Ws, const float* __restrict__ bs,
                        int n) {
    int warp = (blockIdx.x * blockDim.x + threadIdx.x) >> 5;
    int lane = threadIdx.x & 31;
    if (warp >= n) return;
    int t = warp;
    int c = lane * 2;  // this lane owns dims c, c+1; head = lane/8

    float2 q = *reinterpret_cast<const float2*>(g_q1 + t * 64 + c);
    int beg = g_rowptr[t], end = g_rowptr[t + 1];

    float m = -INFINITY, den = 0.f, a0 = 0.f, a1 = 0.f;

    int i = beg;
    float2 kc, vc;
    if (i < end) {
        int s = g_csrsrc[i];
        kc = *reinterpret_cast<const float2*>(g_k1 + s * 64 + c);
        vc = *reinterpret_cast<const float2*>(g_v1 + s * 64 + c);
    }
    while (i < end) {
        // prefetch next edge (MLP=2)
        int i2 = i + 1;
        float2 kn, vn;
        if (i2 < end) {
            int s2 = g_csrsrc[i2];
            kn = *reinterpret_cast<const float2*>(g_k1 + s2 * 64 + c);
            vn = *reinterpret_cast<const float2*>(g_v1 + s2 * 64 + c);
        }
        float p = q.x * kc.x + q.y * kc.y;
        p += __shfl_xor_sync(0xFFFFFFFFu, p, 1);
        p += __shfl_xor_sync(0xFFFFFFFFu, p, 2);
        p += __shfl_xor_sync(0xFFFFFFFFu, p, 4);
        float logit = p * 0.25f;  // / sqrt(16)
        float mn = fmaxf(m, logit);
        float sc = __expf(m - mn);
        float w  = __expf(logit - mn);
        den = den * sc + w;
        a0  = a0  * sc + w * vc.x;
        a1  = a1  * sc + w * vc.y;
        m = mn;
        kc = kn; vc = vn; i = i2;
    }

    float inv = 1.f / (den + 1e-16f);
    float x0 = __ldg(&x[t * 3 + 0]);
    float x1 = __ldg(&x[t * 3 + 1]);
    float x2 = __ldg(&x[t * 3 + 2]);
    float o0 = a0 * inv + bs[c]     + x0 * Ws[c]       + x1 * Ws[64 + c]     + x2 * Ws[128 + c];
    float o1 = a1 * inv + bs[c + 1] + x0 * Ws[c + 1]   + x1 * Ws[64 + c + 1] + x2 * Ws[128 + c + 1];
    *reinterpret_cast<float2*>(g_h + t * 64 + c) =
        make_float2(fmaxf(o0, 0.f), fmaxf(o1, 0.f));
}

// ---------------- layer 2 ----------------

// q2/k2/v2/s2 = h @ W + b  (h: [N,64], W: [64,6]); 4 nodes per 256-thread block
__global__ void k_gemm2(const float* __restrict__ Wq, const float* __restrict__ bq,
                        const float* __restrict__ Wk, const float* __restrict__ bk,
                        const float* __restrict__ Wv, const float* __restrict__ bv,
                        const float* __restrict__ Ws, const float* __restrict__ bs,
                        int n) {
    __shared__ float sh[4][64];
    int local = threadIdx.x >> 6;         // 0..3
    int lane64 = threadIdx.x & 63;
    int node = blockIdx.x * 4 + local;
    if (node < n) sh[local][lane64] = g_h[node * 64 + lane64];
    __syncthreads();
    if (node >= n) return;
    if (lane64 < 24) {
        int mm = lane64 / 6, cc = lane64 % 6;
        const float* W = (mm == 0) ? Wq : (mm == 1) ? Wk : (mm == 2) ? Wv : Ws;
        const float* b = (mm == 0) ? bq : (mm == 1) ? bk : (mm == 2) ? bv : bs;
        float acc = b[cc];
#pragma unroll
        for (int k = 0; k < 64; k++) acc += sh[local][k] * W[k * 6 + cc];
        float* O = (mm == 0) ? g_q2 : (mm == 1) ? g_k2 : (mm == 2) ? g_v2 : g_s2;
        O[node * 6 + cc] = acc;
    }
}

// fused attention layer 2: warp per node, lane per edge, butterfly merge
__global__ void k_attn2(int n) {
    int warp = (blockIdx.x * blockDim.x + threadIdx.x) >> 5;
    int lane = threadIdx.x & 31;
    if (warp >= n) return;
    int t = warp;

    float q[6];
#pragma unroll
    for (int j = 0; j < 6; j++) q[j] = g_q2[t * 6 + j];

    int beg = g_rowptr[t], end = g_rowptr[t + 1];
    float m = -INFINITY, den = 0.f;
    float acc[6] = {0.f, 0.f, 0.f, 0.f, 0.f, 0.f};

    for (int i = beg + lane; i < end; i += 32) {
        int s = g_csrsrc[i];
        const float* kp = g_k2 + s * 6;
        const float* vp = g_v2 + s * 6;
        float p = 0.f;
#pragma unroll
        for (int j = 0; j < 6; j++) p += q[j] * kp[j];
        float logit = p * 0.4082482904638631f;  // 1/sqrt(6)
        float mn = fmaxf(m, logit);
        float sc = __expf(m - mn);
        float w  = __expf(logit - mn);
        den = den * sc + w;
#pragma unroll
        for (int j = 0; j < 6; j++) acc[j] = acc[j] * sc + w * vp[j];
        m = mn;
    }

    // merge 32 per-lane online-softmax states
#pragma unroll
    for (int off = 16; off > 0; off >>= 1) {
        float m2   = __shfl_xor_sync(0xFFFFFFFFu, m,   off);
        float den2 = __shfl_xor_sync(0xFFFFFFFFu, den, off);
        float mn = fmaxf(m, m2);
        float s1 = (den  > 0.f) ? __expf(m  - mn) : 0.f;
        float s2 = (den2 > 0.f) ? __expf(m2 - mn) : 0.f;
#pragma unroll
        for (int j = 0; j < 6; j++) {
            float a2 = __shfl_xor_sync(0xFFFFFFFFu, acc[j], off);
            acc[j] = acc[j] * s1 + a2 * s2;
        }
        den = den * s1 + den2 * s2;
        m = mn;
    }

    if (lane == 0) {
        float inv = 1.f / (den + 1e-16f);
#pragma unroll
        for (int j = 0; j < 6; j++)
            g_o2[t * 6 + j] = acc[j] * inv + g_s2[t * 6 + j];
    }
}

// ---------------- pooling + output ----------------

__global__ void k_pool(const int* __restrict__ batch, int n) {
    __shared__ float ssum[GG * 6];
    __shared__ float scnt[GG];
    __shared__ int   sflag[GG];
    int tid = threadIdx.x;
    for (int i = tid; i < GG * 6; i += blockDim.x) ssum[i] = 0.f;
    for (int i = tid; i < GG; i += blockDim.x) { scnt[i] = 0.f; sflag[i] = 0; }
    __syncthreads();

    int node = blockIdx.x * blockDim.x + tid;
    if (node < n) {
        int g = __ldg(&batch[node]);
#pragma unroll
        for (int c = 0; c < 6; c++)
            atomicAdd(&ssum[g * 6 + c], g_o2[node * 6 + c]);
        atomicAdd(&scnt[g], 1.f);
        sflag[g] = 1;
    }
    __syncthreads();
    for (int g = tid; g < GG; g += blockDim.x) {
        if (sflag[g]) {
            atomicAdd(&g_cnt[g], scnt[g]);
#pragma unroll
            for (int c = 0; c < 6; c++)
                atomicAdd(&g_sums[g * 6 + c], ssum[g * 6 + c]);
        }
    }
}

__global__ void k_out(float* __restrict__ out) {
    int g = threadIdx.x;
    if (g >= GG) return;
    float cnt = fmaxf(g_cnt[g], 1.f);
    float p[6];
    float m = -INFINITY;
#pragma unroll
    for (int c = 0; c < 6; c++) { p[c] = g_sums[g * 6 + c] / cnt; m = fmaxf(m, p[c]); }
    float s = 0.f;
#pragma unroll
    for (int c = 0; c < 6; c++) s += expf(p[c] - m);
    float lse = m + logf(s);
#pragma unroll
    for (int c = 0; c < 6; c++) out[g * 6 + c] = p[c] - lse;
}

// ---------------- launch ----------------
extern "C" void kernel_launch(void* const* d_in, const int* in_sizes, int n_in,
                              void* d_out, int out_size) {
    const float* x    = (const float*)d_in[0];
    const int*   ei   = (const int*)  d_in[1];
    const int*   batch= (const int*)  d_in[2];
    const float* Wq1  = (const float*)d_in[3];
    const float* bq1  = (const float*)d_in[4];
    const float* Wk1  = (const float*)d_in[5];
    const float* bk1  = (const float*)d_in[6];
    const float* Wv1  = (const float*)d_in[7];
    const float* bv1  = (const float*)d_in[8];
    const float* Ws1  = (const float*)d_in[9];
    const float* bs1  = (const float*)d_in[10];
    const float* Wq2  = (const float*)d_in[11];
    const float* bq2  = (const float*)d_in[12];
    const float* Wk2  = (const float*)d_in[13];
    const float* bk2  = (const float*)d_in[14];
    const float* Wv2  = (const float*)d_in[15];
    const float* bv2  = (const float*)d_in[16];
    const float* Ws2  = (const float*)d_in[17];
    const float* bs2  = (const float*)d_in[18];
    float* out = (float*)d_out;

    int N = in_sizes[0] / 3;
    int E = in_sizes[1] / 2;
    const int* src = ei;
    const int* dst = ei + E;

    const int B = 256;
    // CSR build
    k_zero<<<(N + B - 1) / B, B>>>(N);
    k_hist<<<(E + B - 1) / B, B>>>(dst, E);
    k_scan<<<1, 1024>>>(N, E);
    k_scatter<<<(E + B - 1) / B, B>>>(src, dst, E);
    // layer 1
    k_gemm1<<<(N * 64 + B - 1) / B, B>>>(x, Wq1, bq1, Wk1, bk1, Wv1, bv1, N);
    k_attn1<<<(N * 32 + B - 1) / B, B>>>(x, Ws1, bs1, N);
    // layer 2
    k_gemm2<<<(N + 3) / 4, B>>>(Wq2, bq2, Wk2, bk2, Wv2, bv2, Ws2, bs2, N);
    k_attn2<<<(N * 32 + B - 1) / B, B>>>(N);
    // pool + output
    k_pool<<<(N + B - 1) / B, B>>>(batch, N);
    k_out<<<1, 64>>>(out);
}

// round 3
// speedup vs baseline: 2.6692x; 1.1669x over previous
#include <cuda_runtime.h>
#include <math.h>

#define NN 100000
#define EE 3200000
#define GG 64

// ---------------- static device scratch ----------------
__device__ float4 g_x4[NN];          // padded x
__device__ float4 g_cf[NN * 4];      // per (node,head): (e0,e1,e2,d0)
__device__ float  g_h [NN * 64];

__device__ float g_q2[NN * 6];       // pre-scaled by 1/sqrt(6)
__device__ float g_k2[NN * 6];
__device__ float g_v2[NN * 6];
__device__ float g_s2[NN * 6];
__device__ float g_o2[NN * 6];

__device__ int g_deg   [NN];
__device__ int g_rowptr[NN + 1];
__device__ int g_cursor[NN];
__device__ int g_csrsrc[EE];

__device__ float g_sums[GG * 6];
__device__ float g_cnt [GG];

// ---------------- CSR build ----------------

__global__ void k_zero(int n) {
    int i = blockIdx.x * blockDim.x + threadIdx.x;
    if (i < n) g_deg[i] = 0;
    if (i < GG * 6) g_sums[i] = 0.f;
    if (i < GG) g_cnt[i] = 0.f;
}

__global__ void k_hist(const int* __restrict__ dst, int e) {
    int i = blockIdx.x * blockDim.x + threadIdx.x;
    if (i < e) atomicAdd(&g_deg[dst[i]], 1);
}

__global__ void k_scan(int n, int e) {
    __shared__ int ssum[1024];
    int tid = threadIdx.x;
    int chunk = (n + 1023) / 1024;
    int lo = tid * chunk; if (lo > n) lo = n;
    int hi = lo + chunk;  if (hi > n) hi = n;
    int s = 0;
    for (int i = lo; i < hi; i++) s += g_deg[i];
    ssum[tid] = s;
    __syncthreads();
    for (int off = 1; off < 1024; off <<= 1) {
        int v = (tid >= off) ? ssum[tid - off] : 0;
        __syncthreads();
        ssum[tid] += v;
        __syncthreads();
    }
    int run = ssum[tid] - s;
    for (int i = lo; i < hi; i++) {
        int d = g_deg[i];
        g_rowptr[i] = run;
        g_cursor[i] = run;
        run += d;
    }
    if (tid == 0) g_rowptr[n] = e;
}

__global__ void k_scatter(const int* __restrict__ src, const int* __restrict__ dst, int e) {
    int i = blockIdx.x * blockDim.x + threadIdx.x;
    if (i >= e) return;
    int p = atomicAdd(&g_cursor[dst[i]], 1);
    g_csrsrc[p] = src[i];
}

// ---------------- layer-1 prep ----------------

__global__ void k_x4(const float* __restrict__ x, int n) {
    int i = blockIdx.x * blockDim.x + threadIdx.x;
    if (i < n) g_x4[i] = make_float4(x[3 * i], x[3 * i + 1], x[3 * i + 2], 0.f);
}

// per (node, head) bilinear coefficients: logit = (d0 + e . x_src) / 4
__global__ void k_coef(const float* __restrict__ x,
                       const float* __restrict__ Wq, const float* __restrict__ bq,
                       const float* __restrict__ Wk, const float* __restrict__ bk,
                       int n) {
    int idx = blockIdx.x * blockDim.x + threadIdx.x;
    if (idx >= n * 4) return;
    int node = idx >> 2, h = idx & 3;
    float x0 = __ldg(&x[node * 3 + 0]);
    float x1 = __ldg(&x[node * 3 + 1]);
    float x2 = __ldg(&x[node * 3 + 2]);
    float d0 = 0.f, e0 = 0.f, e1 = 0.f, e2 = 0.f;
    int base = h * 16;
#pragma unroll
    for (int c = 0; c < 16; c++) {
        int cc = base + c;
        float qc = bq[cc] + x0 * Wq[cc] + x1 * Wq[64 + cc] + x2 * Wq[128 + cc];
        d0 += qc * bk[cc];
        e0 += qc * Wk[cc];
        e1 += qc * Wk[64 + cc];
        e2 += qc * Wk[128 + cc];
    }
    g_cf[idx] = make_float4(e0, e1, e2, d0);
}

// ---------------- fused attention layer 1 ----------------
// warp per node, lane per edge; two passes (exact max); epilogue reconstructs
// out = (bv*den + Wv . sx)/den + skip, relu -> g_h

__global__ void k_attn1(const float* __restrict__ Wv, const float* __restrict__ bv,
                        const float* __restrict__ Ws, const float* __restrict__ bs,
                        int n) {
    int warp = (blockIdx.x * blockDim.x + threadIdx.x) >> 5;
    int lane = threadIdx.x & 31;
    if (warp >= n) return;
    int t = warp;

    float4 cf0 = g_cf[t * 4 + 0];
    float4 cf1 = g_cf[t * 4 + 1];
    float4 cf2 = g_cf[t * 4 + 2];
    float4 cf3 = g_cf[t * 4 + 3];
    int beg = g_rowptr[t], end = g_rowptr[t + 1];

    // pass A: per-head max of (unscaled) logits
    float m0 = -INFINITY, m1 = -INFINITY, m2 = -INFINITY, m3 = -INFINITY;
    for (int i = beg + lane; i < end; i += 32) {
        int s = g_csrsrc[i];
        float4 xs = g_x4[s];
        m0 = fmaxf(m0, cf0.w + cf0.x * xs.x + cf0.y * xs.y + cf0.z * xs.z);
        m1 = fmaxf(m1, cf1.w + cf1.x * xs.x + cf1.y * xs.y + cf1.z * xs.z);
        m2 = fmaxf(m2, cf2.w + cf2.x * xs.x + cf2.y * xs.y + cf2.z * xs.z);
        m3 = fmaxf(m3, cf3.w + cf3.x * xs.x + cf3.y * xs.y + cf3.z * xs.z);
    }
#pragma unroll
    for (int off = 16; off > 0; off >>= 1) {
        m0 = fmaxf(m0, __shfl_xor_sync(0xFFFFFFFFu, m0, off));
        m1 = fmaxf(m1, __shfl_xor_sync(0xFFFFFFFFu, m1, off));
        m2 = fmaxf(m2, __shfl_xor_sync(0xFFFFFFFFu, m2, off));
        m3 = fmaxf(m3, __shfl_xor_sync(0xFFFFFFFFu, m3, off));
    }

    // pass B: exp and accumulate den, sx (weighted x sums) per head
    float d0 = 0.f, d1 = 0.f, d2 = 0.f, d3 = 0.f;
    float a00 = 0.f, a01 = 0.f, a02 = 0.f;
    float a10 = 0.f, a11 = 0.f, a12 = 0.f;
    float a20 = 0.f, a21 = 0.f, a22 = 0.f;
    float a30 = 0.f, a31 = 0.f, a32 = 0.f;
    for (int i = beg + lane; i < end; i += 32) {
        int s = g_csrsrc[i];
        float4 xs = g_x4[s];
        float l0 = cf0.w + cf0.x * xs.x + cf0.y * xs.y + cf0.z * xs.z;
        float l1 = cf1.w + cf1.x * xs.x + cf1.y * xs.y + cf1.z * xs.z;
        float l2 = cf2.w + cf2.x * xs.x + cf2.y * xs.y + cf2.z * xs.z;
        float l3 = cf3.w + cf3.x * xs.x + cf3.y * xs.y + cf3.z * xs.z;
        float w0 = __expf((l0 - m0) * 0.25f);
        float w1 = __expf((l1 - m1) * 0.25f);
        float w2 = __expf((l2 - m2) * 0.25f);
        float w3 = __expf((l3 - m3) * 0.25f);
        d0 += w0; a00 += w0 * xs.x; a01 += w0 * xs.y; a02 += w0 * xs.z;
        d1 += w1; a10 += w1 * xs.x; a11 += w1 * xs.y; a12 += w1 * xs.z;
        d2 += w2; a20 += w2 * xs.x; a21 += w2 * xs.y; a22 += w2 * xs.z;
        d3 += w3; a30 += w3 * xs.x; a31 += w3 * xs.y; a32 += w3 * xs.z;
    }
#pragma unroll
    for (int off = 16; off > 0; off >>= 1) {
        d0 += __shfl_xor_sync(0xFFFFFFFFu, d0, off);
        d1 += __shfl_xor_sync(0xFFFFFFFFu, d1, off);
        d2 += __shfl_xor_sync(0xFFFFFFFFu, d2, off);
        d3 += __shfl_xor_sync(0xFFFFFFFFu, d3, off);
        a00 += __shfl_xor_sync(0xFFFFFFFFu, a00, off);
        a01 += __shfl_xor_sync(0xFFFFFFFFu, a01, off);
        a02 += __shfl_xor_sync(0xFFFFFFFFu, a02, off);
        a10 += __shfl_xor_sync(0xFFFFFFFFu, a10, off);
        a11 += __shfl_xor_sync(0xFFFFFFFFu, a11, off);
        a12 += __shfl_xor_sync(0xFFFFFFFFu, a12, off);
        a20 += __shfl_xor_sync(0xFFFFFFFFu, a20, off);
        a21 += __shfl_xor_sync(0xFFFFFFFFu, a21, off);
        a22 += __shfl_xor_sync(0xFFFFFFFFu, a22, off);
        a30 += __shfl_xor_sync(0xFFFFFFFFu, a30, off);
        a31 += __shfl_xor_sync(0xFFFFFFFFu, a31, off);
        a32 += __shfl_xor_sync(0xFFFFFFFFu, a32, off);
    }

    // epilogue: lane owns dims c, c+1; head = lane/8
    int c = lane * 2;
    int h = lane >> 3;
    float denh = (h == 0) ? d0 : (h == 1) ? d1 : (h == 2) ? d2 : d3;
    float sxa  = (h == 0) ? a00 : (h == 1) ? a10 : (h == 2) ? a20 : a30;
    float sxb  = (h == 0) ? a01 : (h == 1) ? a11 : (h == 2) ? a21 : a31;
    float sxc  = (h == 0) ? a02 : (h == 1) ? a12 : (h == 2) ? a22 : a32;
    float inv = 1.f / (denh + 1e-16f);

    float4 xt = g_x4[t];
    float o[2];
#pragma unroll
    for (int k = 0; k < 2; k++) {
        int cc = c + k;
        float num = bv[cc] * denh + Wv[cc] * sxa + Wv[64 + cc] * sxb + Wv[128 + cc] * sxc;
        float val = num * inv + bs[cc] + xt.x * Ws[cc] + xt.y * Ws[64 + cc] + xt.z * Ws[128 + cc];
        o[k] = fmaxf(val, 0.f);
    }
    *reinterpret_cast<float2*>(g_h + t * 64 + c) = make_float2(o[0], o[1]);
}

// ---------------- layer 2 ----------------

// q2 (pre-scaled)/k2/v2/s2 = h @ W + b ; 4 nodes per 256-thread block
__global__ void k_gemm2(const float* __restrict__ Wq, const float* __restrict__ bq,
                        const float* __restrict__ Wk, const float* __restrict__ bk,
                        const float* __restrict__ Wv, const float* __restrict__ bv,
                        const float* __restrict__ Ws, const float* __restrict__ bs,
                        int n) {
    __shared__ float sh[4][64];
    int local = threadIdx.x >> 6;
    int lane64 = threadIdx.x & 63;
    int node = blockIdx.x * 4 + local;
    if (node < n) sh[local][lane64] = g_h[node * 64 + lane64];
    __syncthreads();
    if (node >= n) return;
    if (lane64 < 24) {
        int mm = lane64 / 6, cc = lane64 % 6;
        const float* W = (mm == 0) ? Wq : (mm == 1) ? Wk : (mm == 2) ? Wv : Ws;
        const float* b = (mm == 0) ? bq : (mm == 1) ? bk : (mm == 2) ? bv : bs;
        float acc = b[cc];
#pragma unroll
        for (int k = 0; k < 64; k++) acc += sh[local][k] * W[k * 6 + cc];
        if (mm == 0) g_q2[node * 6 + cc] = acc * 0.4082482904638631f;  // 1/sqrt(6)
        else if (mm == 1) g_k2[node * 6 + cc] = acc;
        else if (mm == 2) g_v2[node * 6 + cc] = acc;
        else              g_s2[node * 6 + cc] = acc;
    }
}

// fused attention layer 2: warp per node, two passes
__global__ void k_attn2(int n) {
    int warp = (blockIdx.x * blockDim.x + threadIdx.x) >> 5;
    int lane = threadIdx.x & 31;
    if (warp >= n) return;
    int t = warp;

    float q[6];
#pragma unroll
    for (int j = 0; j < 6; j++) q[j] = g_q2[t * 6 + j];  // already scaled

    int beg = g_rowptr[t], end = g_rowptr[t + 1];

    // pass A: max
    float m = -INFINITY;
    for (int i = beg + lane; i < end; i += 32) {
        int s = g_csrsrc[i];
        const float* kp = g_k2 + s * 6;
        float p = 0.f;
#pragma unroll
        for (int j = 0; j < 6; j++) p += q[j] * kp[j];
        m = fmaxf(m, p);
    }
#pragma unroll
    for (int off = 16; off > 0; off >>= 1)
        m = fmaxf(m, __shfl_xor_sync(0xFFFFFFFFu, m, off));

    // pass B: exp + accumulate
    float den = 0.f;
    float acc[6] = {0.f, 0.f, 0.f, 0.f, 0.f, 0.f};
    for (int i = beg + lane; i < end; i += 32) {
        int s = g_csrsrc[i];
        const float* kp = g_k2 + s * 6;
        const float* vp = g_v2 + s * 6;
        float p = 0.f;
#pragma unroll
        for (int j = 0; j < 6; j++) p += q[j] * kp[j];
        float w = __expf(p - m);
        den += w;
#pragma unroll
        for (int j = 0; j < 6; j++) acc[j] += w * vp[j];
    }
#pragma unroll
    for (int off = 16; off > 0; off >>= 1) {
        den += __shfl_xor_sync(0xFFFFFFFFu, den, off);
#pragma unroll
        for (int j = 0; j < 6; j++)
            acc[j] += __shfl_xor_sync(0xFFFFFFFFu, acc[j], off);
    }

    if (lane == 0) {
        float inv = 1.f / (den + 1e-16f);
#pragma unroll
        for (int j = 0; j < 6; j++)
            g_o2[t * 6 + j] = acc[j] * inv + g_s2[t * 6 + j];
    }
}

// ---------------- pooling + output ----------------

__global__ void k_pool(const int* __restrict__ batch, int n) {
    __shared__ float ssum[GG * 6];
    __shared__ float scnt[GG];
    __shared__ int   sflag[GG];
    int tid = threadIdx.x;
    for (int i = tid; i < GG * 6; i += blockDim.x) ssum[i] = 0.f;
    for (int i = tid; i < GG; i += blockDim.x) { scnt[i] = 0.f; sflag[i] = 0; }
    __syncthreads();

    int node = blockIdx.x * blockDim.x + tid;
    if (node < n) {
        int g = __ldg(&batch[node]);
#pragma unroll
        for (int c = 0; c < 6; c++)
            atomicAdd(&ssum[g * 6 + c], g_o2[node * 6 + c]);
        atomicAdd(&scnt[g], 1.f);
        sflag[g] = 1;
    }
    __syncthreads();
    for (int g = tid; g < GG; g += blockDim.x) {
        if (sflag[g]) {
            atomicAdd(&g_cnt[g], scnt[g]);
#pragma unroll
            for (int c = 0; c < 6; c++)
                atomicAdd(&g_sums[g * 6 + c], ssum[g * 6 + c]);
        }
    }
}

__global__ void k_out(float* __restrict__ out) {
    int g = threadIdx.x;
    if (g >= GG) return;
    float cnt = fmaxf(g_cnt[g], 1.f);
    float p[6];
    float m = -INFINITY;
#pragma unroll
    for (int c = 0; c < 6; c++) { p[c] = g_sums[g * 6 + c] / cnt; m = fmaxf(m, p[c]); }
    float s = 0.f;
#pragma unroll
    for (int c = 0; c < 6; c++) s += expf(p[c] - m);
    float lse = m + logf(s);
#pragma unroll
    for (int c = 0; c < 6; c++) out[g * 6 + c] = p[c] - lse;
}

// ---------------- launch ----------------
extern "C" void kernel_launch(void* const* d_in, const int* in_sizes, int n_in,
                              void* d_out, int out_size) {
    const float* x    = (const float*)d_in[0];
    const int*   ei   = (const int*)  d_in[1];
    const int*   batch= (const int*)  d_in[2];
    const float* Wq1  = (const float*)d_in[3];
    const float* bq1  = (const float*)d_in[4];
    const float* Wk1  = (const float*)d_in[5];
    const float* bk1  = (const float*)d_in[6];
    const float* Wv1  = (const float*)d_in[7];
    const float* bv1  = (const float*)d_in[8];
    const float* Ws1  = (const float*)d_in[9];
    const float* bs1  = (const float*)d_in[10];
    const float* Wq2  = (const float*)d_in[11];
    const float* bq2  = (const float*)d_in[12];
    const float* Wk2  = (const float*)d_in[13];
    const float* bk2  = (const float*)d_in[14];
    const float* Wv2  = (const float*)d_in[15];
    const float* bv2  = (const float*)d_in[16];
    const float* Ws2  = (const float*)d_in[17];
    const float* bs2  = (const float*)d_in[18];
    float* out = (float*)d_out;

    int N = in_sizes[0] / 3;
    int E = in_sizes[1] / 2;
    const int* src = ei;
    const int* dst = ei + E;

    const int B = 256;
    // CSR build + layer-1 prep (independent kernels)
    k_zero<<<(N + B - 1) / B, B>>>(N);
    k_hist<<<(E + B - 1) / B, B>>>(dst, E);
    k_x4  <<<(N + B - 1) / B, B>>>(x, N);
    k_coef<<<(N * 4 + B - 1) / B, B>>>(x, Wq1, bq1, Wk1, bk1, N);
    k_scan<<<1, 1024>>>(N, E);
    k_scatter<<<(E + B - 1) / B, B>>>(src, dst, E);
    // layer 1 (fused)
    k_attn1<<<(N * 32 + B - 1) / B, B>>>(Wv1, bv1, Ws1, bs1, N);
    // layer 2
    k_gemm2<<<(N + 3) / 4, B>>>(Wq2, bq2, Wk2, bk2, Wv2, bv2, Ws2, bs2, N);
    k_attn2<<<(N * 32 + B - 1) / B, B>>>(N);
    // pool + output
    k_pool<<<(N + B - 1) / B, B>>>(batch, N);
    k_out<<<1, 64>>>(out);
}

// round 5
// speedup vs baseline: 3.0588x; 1.1459x over previous
#include <cuda_runtime.h>
#include <math.h>

#define NN 100000
#define EE 3200000
#define GG 64

// ---------------- static device scratch ----------------
__device__ float4 g_x4[NN];          // padded x
__device__ float4 g_cf[NN * 4];      // per (node,head): (e0,e1,e2,d0)
__device__ float  g_h [NN * 64];

__device__ float g_kv[NN * 16];      // [0..5]=k2, [6..11]=v2, pad to 64B
__device__ float g_qs[NN * 16];      // [0..5]=q2 (pre-scaled), [8..13]=s2
__device__ float g_o2[NN * 6];

__device__ int g_deg   [NN];
__device__ int g_rowptr[NN + 1];
__device__ int g_cursor[NN];
__device__ int g_csrsrc[EE];

__device__ float g_sums[GG * 6];
__device__ float g_cnt [GG];

// warp reductions via shuffle butterfly (redux.f32 not available on sm_100)
__device__ __forceinline__ float warp_sum(float v) {
#pragma unroll
    for (int off = 16; off > 0; off >>= 1)
        v += __shfl_xor_sync(0xFFFFFFFFu, v, off);
    return v;
}
__device__ __forceinline__ float warp_max(float v) {
#pragma unroll
    for (int off = 16; off > 0; off >>= 1)
        v = fmaxf(v, __shfl_xor_sync(0xFFFFFFFFu, v, off));
    return v;
}

// ---------------- fused prep: zero + x4 + coef ----------------
__global__ void k_prep(const float* __restrict__ x,
                       const float* __restrict__ Wq, const float* __restrict__ bq,
                       const float* __restrict__ Wk, const float* __restrict__ bk,
                       int n) {
    int idx = blockIdx.x * blockDim.x + threadIdx.x;
    if (idx < GG * 6) g_sums[idx] = 0.f;
    if (idx < GG) g_cnt[idx] = 0.f;
    if (idx >= n * 4) return;
    int node = idx >> 2, h = idx & 3;
    float x0 = __ldg(&x[node * 3 + 0]);
    float x1 = __ldg(&x[node * 3 + 1]);
    float x2 = __ldg(&x[node * 3 + 2]);
    if (h == 0) {
        g_deg[node] = 0;
        g_x4[node] = make_float4(x0, x1, x2, 0.f);
    }
    float d0 = 0.f, e0 = 0.f, e1 = 0.f, e2 = 0.f;
    int base = h * 16;
#pragma unroll
    for (int c = 0; c < 16; c++) {
        int cc = base + c;
        float qc = bq[cc] + x0 * Wq[cc] + x1 * Wq[64 + cc] + x2 * Wq[128 + cc];
        d0 += qc * bk[cc];
        e0 += qc * Wk[cc];
        e1 += qc * Wk[64 + cc];
        e2 += qc * Wk[128 + cc];
    }
    g_cf[idx] = make_float4(e0, e1, e2, d0);
}

// ---------------- CSR build ----------------
__global__ void k_hist(const int* __restrict__ dst, int e) {
    int i = blockIdx.x * blockDim.x + threadIdx.x;
    if (i < e) atomicAdd(&g_deg[dst[i]], 1);
}

__global__ void k_scan(int n, int e) {
    __shared__ int ssum[1024];
    int tid = threadIdx.x;
    int chunk = (n + 1023) / 1024;
    int lo = tid * chunk; if (lo > n) lo = n;
    int hi = lo + chunk;  if (hi > n) hi = n;
    int s = 0;
    for (int i = lo; i < hi; i++) s += g_deg[i];
    ssum[tid] = s;
    __syncthreads();
    for (int off = 1; off < 1024; off <<= 1) {
        int v = (tid >= off) ? ssum[tid - off] : 0;
        __syncthreads();
        ssum[tid] += v;
        __syncthreads();
    }
    int run = ssum[tid] - s;
    for (int i = lo; i < hi; i++) {
        int d = g_deg[i];
        g_rowptr[i] = run;
        g_cursor[i] = run;
        run += d;
    }
    if (tid == 0) g_rowptr[n] = e;
}

__global__ void k_scatter(const int* __restrict__ src, const int* __restrict__ dst, int e) {
    int i = blockIdx.x * blockDim.x + threadIdx.x;
    if (i >= e) return;
    int p = atomicAdd(&g_cursor[dst[i]], 1);
    g_csrsrc[p] = src[i];
}

// ---------------- fused attention layer 1 ----------------
__global__ void k_attn1(const float* __restrict__ Wv, const float* __restrict__ bv,
                        const float* __restrict__ Ws, const float* __restrict__ bs,
                        int n) {
    int warp = (blockIdx.x * blockDim.x + threadIdx.x) >> 5;
    int lane = threadIdx.x & 31;
    if (warp >= n) return;
    int t = warp;

    float4 cf0 = g_cf[t * 4 + 0];
    float4 cf1 = g_cf[t * 4 + 1];
    float4 cf2 = g_cf[t * 4 + 2];
    float4 cf3 = g_cf[t * 4 + 3];
    int beg = g_rowptr[t], end = g_rowptr[t + 1];

    // pass A: per-head max of unscaled logits
    float m0 = -INFINITY, m1 = -INFINITY, m2 = -INFINITY, m3 = -INFINITY;
    for (int i = beg + lane; i < end; i += 32) {
        int s = g_csrsrc[i];
        float4 xs = g_x4[s];
        m0 = fmaxf(m0, cf0.w + cf0.x * xs.x + cf0.y * xs.y + cf0.z * xs.z);
        m1 = fmaxf(m1, cf1.w + cf1.x * xs.x + cf1.y * xs.y + cf1.z * xs.z);
        m2 = fmaxf(m2, cf2.w + cf2.x * xs.x + cf2.y * xs.y + cf2.z * xs.z);
        m3 = fmaxf(m3, cf3.w + cf3.x * xs.x + cf3.y * xs.y + cf3.z * xs.z);
    }
    m0 = warp_max(m0); m1 = warp_max(m1); m2 = warp_max(m2); m3 = warp_max(m3);

    // pass B: exp + accumulate den and weighted x sums per head
    float d0 = 0.f, d1 = 0.f, d2 = 0.f, d3 = 0.f;
    float a00 = 0.f, a01 = 0.f, a02 = 0.f;
    float a10 = 0.f, a11 = 0.f, a12 = 0.f;
    float a20 = 0.f, a21 = 0.f, a22 = 0.f;
    float a30 = 0.f, a31 = 0.f, a32 = 0.f;
    for (int i = beg + lane; i < end; i += 32) {
        int s = g_csrsrc[i];
        float4 xs = g_x4[s];
        float l0 = cf0.w + cf0.x * xs.x + cf0.y * xs.y + cf0.z * xs.z;
        float l1 = cf1.w + cf1.x * xs.x + cf1.y * xs.y + cf1.z * xs.z;
        float l2 = cf2.w + cf2.x * xs.x + cf2.y * xs.y + cf2.z * xs.z;
        float l3 = cf3.w + cf3.x * xs.x + cf3.y * xs.y + cf3.z * xs.z;
        float w0 = __expf((l0 - m0) * 0.25f);
        float w1 = __expf((l1 - m1) * 0.25f);
        float w2 = __expf((l2 - m2) * 0.25f);
        float w3 = __expf((l3 - m3) * 0.25f);
        d0 += w0; a00 += w0 * xs.x; a01 += w0 * xs.y; a02 += w0 * xs.z;
        d1 += w1; a10 += w1 * xs.x; a11 += w1 * xs.y; a12 += w1 * xs.z;
        d2 += w2; a20 += w2 * xs.x; a21 += w2 * xs.y; a22 += w2 * xs.z;
        d3 += w3; a30 += w3 * xs.x; a31 += w3 * xs.y; a32 += w3 * xs.z;
    }
#pragma unroll
    for (int off = 16; off > 0; off >>= 1) {
        d0 += __shfl_xor_sync(0xFFFFFFFFu, d0, off);
        d1 += __shfl_xor_sync(0xFFFFFFFFu, d1, off);
        d2 += __shfl_xor_sync(0xFFFFFFFFu, d2, off);
        d3 += __shfl_xor_sync(0xFFFFFFFFu, d3, off);
        a00 += __shfl_xor_sync(0xFFFFFFFFu, a00, off);
        a01 += __shfl_xor_sync(0xFFFFFFFFu, a01, off);
        a02 += __shfl_xor_sync(0xFFFFFFFFu, a02, off);
        a10 += __shfl_xor_sync(0xFFFFFFFFu, a10, off);
        a11 += __shfl_xor_sync(0xFFFFFFFFu, a11, off);
        a12 += __shfl_xor_sync(0xFFFFFFFFu, a12, off);
        a20 += __shfl_xor_sync(0xFFFFFFFFu, a20, off);
        a21 += __shfl_xor_sync(0xFFFFFFFFu, a21, off);
        a22 += __shfl_xor_sync(0xFFFFFFFFu, a22, off);
        a30 += __shfl_xor_sync(0xFFFFFFFFu, a30, off);
        a31 += __shfl_xor_sync(0xFFFFFFFFu, a31, off);
        a32 += __shfl_xor_sync(0xFFFFFFFFu, a32, off);
    }

    // epilogue: lane owns dims c, c+1; head = lane/8
    int c = lane * 2;
    int h = lane >> 3;
    float denh = (h == 0) ? d0 : (h == 1) ? d1 : (h == 2) ? d2 : d3;
    float sxa  = (h == 0) ? a00 : (h == 1) ? a10 : (h == 2) ? a20 : a30;
    float sxb  = (h == 0) ? a01 : (h == 1) ? a11 : (h == 2) ? a21 : a31;
    float sxc  = (h == 0) ? a02 : (h == 1) ? a12 : (h == 2) ? a22 : a32;
    float inv = 1.f / (denh + 1e-16f);

    float4 xt = g_x4[t];
    float o[2];
#pragma unroll
    for (int k = 0; k < 2; k++) {
        int cc = c + k;
        float num = bv[cc] * denh + Wv[cc] * sxa + Wv[64 + cc] * sxb + Wv[128 + cc] * sxc;
        float val = num * inv + bs[cc] + xt.x * Ws[cc] + xt.y * Ws[64 + cc] + xt.z * Ws[128 + cc];
        o[k] = fmaxf(val, 0.f);
    }
    *reinterpret_cast<float2*>(g_h + t * 64 + c) = make_float2(o[0], o[1]);
}

// ---------------- layer 2 projection ----------------
// 8 nodes per 256-thread block, warp per node; weights staged in shared.
__global__ void k_gemm2(const float* __restrict__ Wq, const float* __restrict__ bq,
                        const float* __restrict__ Wk, const float* __restrict__ bk,
                        const float* __restrict__ Wv, const float* __restrict__ bv,
                        const float* __restrict__ Ws, const float* __restrict__ bs,
                        int n) {
    __shared__ float shH[8][64];
    __shared__ float shW[4][390];   // 384 used, padded
    __shared__ float shB[4][6];
    int tid = threadIdx.x;
    int blk = blockIdx.x;

    for (int i = tid; i < 384 * 4; i += 256) {
        int mm = i / 384, r = i % 384;
        const float* W = (mm == 0) ? Wq : (mm == 1) ? Wk : (mm == 2) ? Wv : Ws;
        shW[mm][r] = W[r];
    }
    if (tid < 24) {
        int mm = tid / 6, cc = tid % 6;
        const float* b = (mm == 0) ? bq : (mm == 1) ? bk : (mm == 2) ? bv : bs;
        shB[mm][cc] = b[cc];
    }
    int base = blk * 8 * 64;
#pragma unroll
    for (int r = 0; r < 2; r++) {
        int i = tid + r * 256;
        int node = blk * 8 + (i >> 6);
        shH[i >> 6][i & 63] = (node < n) ? g_h[base + i] : 0.f;
    }
    __syncthreads();

    int w = tid >> 5;
    int lane = tid & 31;
    int node = blk * 8 + w;
    if (node >= n || lane >= 24) return;
    int mm = lane / 6, cc = lane % 6;
    float acc = shB[mm][cc];
#pragma unroll
    for (int k = 0; k < 64; k++) acc += shH[w][k] * shW[mm][k * 6 + cc];
    if (mm == 0)      g_qs[node * 16 + cc]     = acc * 0.4082482904638631f;  // q / sqrt(6)
    else if (mm == 1) g_kv[node * 16 + cc]     = acc;                        // k
    else if (mm == 2) g_kv[node * 16 + 6 + cc] = acc;                        // v
    else              g_qs[node * 16 + 8 + cc] = acc;                        // s
}

// ---------------- fused attention layer 2 ----------------
__global__ void k_attn2(int n) {
    int warp = (blockIdx.x * blockDim.x + threadIdx.x) >> 5;
    int lane = threadIdx.x & 31;
    if (warp >= n) return;
    int t = warp;

    float q[6];
#pragma unroll
    for (int j = 0; j < 6; j++) q[j] = g_qs[t * 16 + j];   // pre-scaled

    const float4* kv4 = reinterpret_cast<const float4*>(g_kv);
    int beg = g_rowptr[t], end = g_rowptr[t + 1];

    // pass A: max logit
    float m = -INFINITY;
    for (int i = beg + lane; i < end; i += 32) {
        int s = g_csrsrc[i];
        float4 f0 = kv4[s * 4 + 0];
        float4 f1 = kv4[s * 4 + 1];
        float p = q[0] * f0.x + q[1] * f0.y + q[2] * f0.z + q[3] * f0.w
                + q[4] * f1.x + q[5] * f1.y;
        m = fmaxf(m, p);
    }
    m = warp_max(m);

    // pass B: exp + accumulate
    float den = 0.f;
    float acc[6] = {0.f, 0.f, 0.f, 0.f, 0.f, 0.f};
    for (int i = beg + lane; i < end; i += 32) {
        int s = g_csrsrc[i];
        float4 f0 = kv4[s * 4 + 0];
        float4 f1 = kv4[s * 4 + 1];
        float4 f2 = kv4[s * 4 + 2];
        float p = q[0] * f0.x + q[1] * f0.y + q[2] * f0.z + q[3] * f0.w
                + q[4] * f1.x + q[5] * f1.y;
        float w = __expf(p - m);
        den += w;
        acc[0] += w * f1.z; acc[1] += w * f1.w;
        acc[2] += w * f2.x; acc[3] += w * f2.y;
        acc[4] += w * f2.z; acc[5] += w * f2.w;
    }
    den = warp_sum(den);
#pragma unroll
    for (int j = 0; j < 6; j++) acc[j] = warp_sum(acc[j]);

    if (lane == 0) {
        float inv = 1.f / (den + 1e-16f);
#pragma unroll
        for (int j = 0; j < 6; j++)
            g_o2[t * 6 + j] = acc[j] * inv + g_qs[t * 16 + 8 + j];
    }
}

// ---------------- pooling + output ----------------
__global__ void k_pool(const int* __restrict__ batch, int n) {
    __shared__ float ssum[GG * 6];
    __shared__ float scnt[GG];
    __shared__ int   sflag[GG];
    int tid = threadIdx.x;
    for (int i = tid; i < GG * 6; i += blockDim.x) ssum[i] = 0.f;
    for (int i = tid; i < GG; i += blockDim.x) { scnt[i] = 0.f; sflag[i] = 0; }
    __syncthreads();

    int node = blockIdx.x * blockDim.x + tid;
    if (node < n) {
        int g = __ldg(&batch[node]);
#pragma unroll
        for (int c = 0; c < 6; c++)
            atomicAdd(&ssum[g * 6 + c], g_o2[node * 6 + c]);
        atomicAdd(&scnt[g], 1.f);
        sflag[g] = 1;
    }
    __syncthreads();
    for (int g = tid; g < GG; g += blockDim.x) {
        if (sflag[g]) {
            atomicAdd(&g_cnt[g], scnt[g]);
#pragma unroll
            for (int c = 0; c < 6; c++)
                atomicAdd(&g_sums[g * 6 + c], ssum[g * 6 + c]);
        }
    }
}

__global__ void k_out(float* __restrict__ out) {
    int g = threadIdx.x;
    if (g >= GG) return;
    float cnt = fmaxf(g_cnt[g], 1.f);
    float p[6];
    float m = -INFINITY;
#pragma unroll
    for (int c = 0; c < 6; c++) { p[c] = g_sums[g * 6 + c] / cnt; m = fmaxf(m, p[c]); }
    float s = 0.f;
#pragma unroll
    for (int c = 0; c < 6; c++) s += expf(p[c] - m);
    float lse = m + logf(s);
#pragma unroll
    for (int c = 0; c < 6; c++) out[g * 6 + c] = p[c] - lse;
}

// ---------------- launch ----------------
extern "C" void kernel_launch(void* const* d_in, const int* in_sizes, int n_in,
                              void* d_out, int out_size) {
    const float* x    = (const float*)d_in[0];
    const int*   ei   = (const int*)  d_in[1];
    const int*   batch= (const int*)  d_in[2];
    const float* Wq1  = (const float*)d_in[3];
    const float* bq1  = (const float*)d_in[4];
    const float* Wk1  = (const float*)d_in[5];
    const float* bk1  = (const float*)d_in[6];
    const float* Wv1  = (const float*)d_in[7];
    const float* bv1  = (const float*)d_in[8];
    const float* Ws1  = (const float*)d_in[9];
    const float* bs1  = (const float*)d_in[10];
    const float* Wq2  = (const float*)d_in[11];
    const float* bq2  = (const float*)d_in[12];
    const float* Wk2  = (const float*)d_in[13];
    const float* bk2  = (const float*)d_in[14];
    const float* Wv2  = (const float*)d_in[15];
    const float* bv2  = (const float*)d_in[16];
    const float* Ws2  = (const float*)d_in[17];
    const float* bs2  = (const float*)d_in[18];
    float* out = (float*)d_out;

    int N = in_sizes[0] / 3;
    int E = in_sizes[1] / 2;
    const int* src = ei;
    const int* dst = ei + E;

    const int B = 256;
    k_prep<<<(N * 4 + B - 1) / B, B>>>(x, Wq1, bq1, Wk1, bk1, N);
    k_hist<<<(E + B - 1) / B, B>>>(dst, E);
    k_scan<<<1, 1024>>>(N, E);
    k_scatter<<<(E + B - 1) / B, B>>>(src, dst, E);
    k_attn1<<<(N * 32 + B - 1) / B, B>>>(Wv1, bv1, Ws1, bs1, N);
    k_gemm2<<<(N + 7) / 8, B>>>(Wq2, bq2, Wk2, bk2, Wv2, bv2, Ws2, bs2, N);
    k_attn2<<<(N * 32 + B - 1) / B, B>>>(N);
    k_pool<<<(N + B - 1) / B, B>>>(batch, N);
    k_out<<<1, 64>>>(out);
}

// round 6
// speedup vs baseline: 4.2382x; 1.3856x over previous
#include <cuda_runtime.h>
#include <math.h>

#define NN 100000
#define EE 3200000
#define GG 64

// ---------------- static device scratch ----------------
__device__ float4 g_x4[NN];          // padded x
__device__ float4 g_cf[NN * 4];      // per (node,head): (e0,e1,e2,d0)
__device__ float  g_h [NN * 64];

__device__ float g_kv[NN * 16];      // [0..5]=k2, [6..11]=v2, pad to 64B
__device__ float g_qs[NN * 16];      // [0..5]=q2 (pre-scaled), [8..13]=s2
__device__ float g_o2[NN * 6];

__device__ int g_deg   [NN];
__device__ int g_rowptr[NN + 1];
__device__ int g_cursor[NN];
__device__ int g_csrsrc[EE];
__device__ int g_bsum[128];
__device__ int g_boff[128];

__device__ float g_sums[GG * 6];
__device__ float g_cnt [GG];

__device__ __forceinline__ float warp_sum(float v) {
#pragma unroll
    for (int off = 16; off > 0; off >>= 1)
        v += __shfl_xor_sync(0xFFFFFFFFu, v, off);
    return v;
}

// ---------------- fused prep: zero + x4 + coef ----------------
__global__ void k_prep(const float* __restrict__ x,
                       const float* __restrict__ Wq, const float* __restrict__ bq,
                       const float* __restrict__ Wk, const float* __restrict__ bk,
                       int n) {
    int idx = blockIdx.x * blockDim.x + threadIdx.x;
    if (idx < GG * 6) g_sums[idx] = 0.f;
    if (idx < GG) g_cnt[idx] = 0.f;
    if (idx >= n * 4) return;
    int node = idx >> 2, h = idx & 3;
    float x0 = __ldg(&x[node * 3 + 0]);
    float x1 = __ldg(&x[node * 3 + 1]);
    float x2 = __ldg(&x[node * 3 + 2]);
    if (h == 0) {
        g_deg[node] = 0;
        g_x4[node] = make_float4(x0, x1, x2, 0.f);
    }
    float d0 = 0.f, e0 = 0.f, e1 = 0.f, e2 = 0.f;
    int base = h * 16;
#pragma unroll
    for (int c = 0; c < 16; c++) {
        int cc = base + c;
        float qc = bq[cc] + x0 * Wq[cc] + x1 * Wq[64 + cc] + x2 * Wq[128 + cc];
        d0 += qc * bk[cc];
        e0 += qc * Wk[cc];
        e1 += qc * Wk[64 + cc];
        e2 += qc * Wk[128 + cc];
    }
    g_cf[idx] = make_float4(e0, e1, e2, d0);
}

// ---------------- CSR build ----------------
__global__ void k_hist(const int* __restrict__ dst, int e) {
    int i = blockIdx.x * blockDim.x + threadIdx.x;
    if (i < e) atomicAdd(&g_deg[dst[i]], 1);
}

// coalesced 3-kernel scan
__global__ void k_scan_blk(int n) {
    __shared__ int wsum[32];
    int i = blockIdx.x * 1024 + threadIdx.x;
    int v = (i < n) ? g_deg[i] : 0;
#pragma unroll
    for (int off = 16; off > 0; off >>= 1)
        v += __shfl_xor_sync(0xFFFFFFFFu, v, off);
    int lane = threadIdx.x & 31, wid = threadIdx.x >> 5;
    if (lane == 0) wsum[wid] = v;
    __syncthreads();
    if (wid == 0) {
        int s = wsum[lane];
#pragma unroll
        for (int off = 16; off > 0; off >>= 1)
            s += __shfl_xor_sync(0xFFFFFFFFu, s, off);
        if (lane == 0) g_bsum[blockIdx.x] = s;
    }
}

__global__ void k_scan_top(int nb) {
    if (threadIdx.x == 0) {
        int run = 0;
        for (int b = 0; b < nb; b++) {
            int t = g_bsum[b];
            g_boff[b] = run;
            run += t;
        }
    }
}

__global__ void k_scan_wr(int n, int e) {
    __shared__ int wsum[32];
    int i = blockIdx.x * 1024 + threadIdx.x;
    int v = (i < n) ? g_deg[i] : 0;
    int lane = threadIdx.x & 31, wid = threadIdx.x >> 5;
    int x = v;
#pragma unroll
    for (int off = 1; off < 32; off <<= 1) {
        int y = __shfl_up_sync(0xFFFFFFFFu, x, off);
        if (lane >= off) x += y;
    }
    if (lane == 31) wsum[wid] = x;
    __syncthreads();
    if (wid == 0) {
        int w = wsum[lane];
#pragma unroll
        for (int off = 1; off < 32; off <<= 1) {
            int y = __shfl_up_sync(0xFFFFFFFFu, w, off);
            if (lane >= off) w += y;
        }
        wsum[lane] = w;
    }
    __syncthreads();
    int excl = x - v + ((wid > 0) ? wsum[wid - 1] : 0) + g_boff[blockIdx.x];
    if (i < n) { g_rowptr[i] = excl; g_cursor[i] = excl; }
    if (i == n) g_rowptr[n] = e;
}

__global__ void k_scatter(const int* __restrict__ src, const int* __restrict__ dst, int e) {
    int i = blockIdx.x * blockDim.x + threadIdx.x;
    if (i >= e) return;
    int p = atomicAdd(&g_cursor[dst[i]], 1);
    g_csrsrc[p] = src[i];
}

// ---------------- fused attention layer 1 (single-pass online softmax) ----------------
__global__ void k_attn1(const float* __restrict__ Wv, const float* __restrict__ bv,
                        const float* __restrict__ Ws, const float* __restrict__ bs,
                        int n) {
    int warp = (blockIdx.x * blockDim.x + threadIdx.x) >> 5;
    int lane = threadIdx.x & 31;
    if (warp >= n) return;
    int t = warp;

    float4 cf0 = g_cf[t * 4 + 0];
    float4 cf1 = g_cf[t * 4 + 1];
    float4 cf2 = g_cf[t * 4 + 2];
    float4 cf3 = g_cf[t * 4 + 3];
    int beg = g_rowptr[t], end = g_rowptr[t + 1];

    // per-lane online state for 4 heads: m (unscaled), den, sx0..sx2
    float m0 = -INFINITY, m1 = -INFINITY, m2 = -INFINITY, m3 = -INFINITY;
    float d0 = 0.f, d1 = 0.f, d2 = 0.f, d3 = 0.f;
    float a00 = 0.f, a01 = 0.f, a02 = 0.f;
    float a10 = 0.f, a11 = 0.f, a12 = 0.f;
    float a20 = 0.f, a21 = 0.f, a22 = 0.f;
    float a30 = 0.f, a31 = 0.f, a32 = 0.f;

    for (int i = beg + lane; i < end; i += 32) {
        int s = g_csrsrc[i];
        float4 xs = g_x4[s];
        float l0 = cf0.w + cf0.x * xs.x + cf0.y * xs.y + cf0.z * xs.z;
        float l1 = cf1.w + cf1.x * xs.x + cf1.y * xs.y + cf1.z * xs.z;
        float l2 = cf2.w + cf2.x * xs.x + cf2.y * xs.y + cf2.z * xs.z;
        float l3 = cf3.w + cf3.x * xs.x + cf3.y * xs.y + cf3.z * xs.z;
        // head 0
        {
            float mn = fmaxf(m0, l0);
            float sc = __expf((m0 - mn) * 0.25f);   // m0=-inf -> 0
            float w  = __expf((l0 - mn) * 0.25f);
            d0 = d0 * sc + w;
            a00 = a00 * sc + w * xs.x; a01 = a01 * sc + w * xs.y; a02 = a02 * sc + w * xs.z;
            m0 = mn;
        }
        {
            float mn = fmaxf(m1, l1);
            float sc = __expf((m1 - mn) * 0.25f);
            float w  = __expf((l1 - mn) * 0.25f);
            d1 = d1 * sc + w;
            a10 = a10 * sc + w * xs.x; a11 = a11 * sc + w * xs.y; a12 = a12 * sc + w * xs.z;
            m1 = mn;
        }
        {
            float mn = fmaxf(m2, l2);
            float sc = __expf((m2 - mn) * 0.25f);
            float w  = __expf((l2 - mn) * 0.25f);
            d2 = d2 * sc + w;
            a20 = a20 * sc + w * xs.x; a21 = a21 * sc + w * xs.y; a22 = a22 * sc + w * xs.z;
            m2 = mn;
        }
        {
            float mn = fmaxf(m3, l3);
            float sc = __expf((m3 - mn) * 0.25f);
            float w  = __expf((l3 - mn) * 0.25f);
            d3 = d3 * sc + w;
            a30 = a30 * sc + w * xs.x; a31 = a31 * sc + w * xs.y; a32 = a32 * sc + w * xs.z;
            m3 = mn;
        }
    }

    // guarded butterfly merge of online states, per head
#pragma unroll
    for (int off = 16; off > 0; off >>= 1) {
        {
            float m2_ = __shfl_xor_sync(0xFFFFFFFFu, m0, off);
            float d2_ = __shfl_xor_sync(0xFFFFFFFFu, d0, off);
            float t0 = __shfl_xor_sync(0xFFFFFFFFu, a00, off);
            float t1 = __shfl_xor_sync(0xFFFFFFFFu, a01, off);
            float t2 = __shfl_xor_sync(0xFFFFFFFFu, a02, off);
            float mn = fmaxf(m0, m2_);
            float sa = (d0  > 0.f) ? __expf((m0  - mn) * 0.25f) : 0.f;
            float sb = (d2_ > 0.f) ? __expf((m2_ - mn) * 0.25f) : 0.f;
            d0 = d0 * sa + d2_ * sb;
            a00 = a00 * sa + t0 * sb; a01 = a01 * sa + t1 * sb; a02 = a02 * sa + t2 * sb;
            m0 = mn;
        }
        {
            float m2_ = __shfl_xor_sync(0xFFFFFFFFu, m1, off);
            float d2_ = __shfl_xor_sync(0xFFFFFFFFu, d1, off);
            float t0 = __shfl_xor_sync(0xFFFFFFFFu, a10, off);
            float t1 = __shfl_xor_sync(0xFFFFFFFFu, a11, off);
            float t2 = __shfl_xor_sync(0xFFFFFFFFu, a12, off);
            float mn = fmaxf(m1, m2_);
            float sa = (d1  > 0.f) ? __expf((m1  - mn) * 0.25f) : 0.f;
            float sb = (d2_ > 0.f) ? __expf((m2_ - mn) * 0.25f) : 0.f;
            d1 = d1 * sa + d2_ * sb;
            a10 = a10 * sa + t0 * sb; a11 = a11 * sa + t1 * sb; a12 = a12 * sa + t2 * sb;
            m1 = mn;
        }
        {
            float m2_ = __shfl_xor_sync(0xFFFFFFFFu, m2, off);
            float d2_ = __shfl_xor_sync(0xFFFFFFFFu, d2, off);
            float t0 = __shfl_xor_sync(0xFFFFFFFFu, a20, off);
            float t1 = __shfl_xor_sync(0xFFFFFFFFu, a21, off);
            float t2 = __shfl_xor_sync(0xFFFFFFFFu, a22, off);
            float mn = fmaxf(m2, m2_);
            float sa = (d2  > 0.f) ? __expf((m2  - mn) * 0.25f) : 0.f;
            float sb = (d2_ > 0.f) ? __expf((m2_ - mn) * 0.25f) : 0.f;
            d2 = d2 * sa + d2_ * sb;
            a20 = a20 * sa + t0 * sb; a21 = a21 * sa + t1 * sb; a22 = a22 * sa + t2 * sb;
            m2 = mn;
        }
        {
            float m2_ = __shfl_xor_sync(0xFFFFFFFFu, m3, off);
            float d2_ = __shfl_xor_sync(0xFFFFFFFFu, d3, off);
            float t0 = __shfl_xor_sync(0xFFFFFFFFu, a30, off);
            float t1 = __shfl_xor_sync(0xFFFFFFFFu, a31, off);
            float t2 = __shfl_xor_sync(0xFFFFFFFFu, a32, off);
            float mn = fmaxf(m3, m2_);
            float sa = (d3  > 0.f) ? __expf((m3  - mn) * 0.25f) : 0.f;
            float sb = (d2_ > 0.f) ? __expf((m2_ - mn) * 0.25f) : 0.f;
            d3 = d3 * sa + d2_ * sb;
            a30 = a30 * sa + t0 * sb; a31 = a31 * sa + t1 * sb; a32 = a32 * sa + t2 * sb;
            m3 = mn;
        }
    }

    // epilogue: lane owns dims c, c+1; head = lane/8
    int c = lane * 2;
    int h = lane >> 3;
    float denh = (h == 0) ? d0 : (h == 1) ? d1 : (h == 2) ? d2 : d3;
    float sxa  = (h == 0) ? a00 : (h == 1) ? a10 : (h == 2) ? a20 : a30;
    float sxb  = (h == 0) ? a01 : (h == 1) ? a11 : (h == 2) ? a21 : a31;
    float sxc  = (h == 0) ? a02 : (h == 1) ? a12 : (h == 2) ? a22 : a32;
    float inv = 1.f / (denh + 1e-16f);

    float4 xt = g_x4[t];
    float o[2];
#pragma unroll
    for (int k = 0; k < 2; k++) {
        int cc = c + k;
        float num = bv[cc] * denh + Wv[cc] * sxa + Wv[64 + cc] * sxb + Wv[128 + cc] * sxc;
        float val = num * inv + bs[cc] + xt.x * Ws[cc] + xt.y * Ws[64 + cc] + xt.z * Ws[128 + cc];
        o[k] = fmaxf(val, 0.f);
    }
    *reinterpret_cast<float2*>(g_h + t * 64 + c) = make_float2(o[0], o[1]);
}

// ---------------- layer 2 projection ----------------
__global__ void k_gemm2(const float* __restrict__ Wq, const float* __restrict__ bq,
                        const float* __restrict__ Wk, const float* __restrict__ bk,
                        const float* __restrict__ Wv, const float* __restrict__ bv,
                        const float* __restrict__ Ws, const float* __restrict__ bs,
                        int n) {
    __shared__ float shH[8][64];
    __shared__ float shW[4][390];
    __shared__ float shB[4][6];
    int tid = threadIdx.x;
    int blk = blockIdx.x;

    for (int i = tid; i < 384 * 4; i += 256) {
        int mm = i / 384, r = i % 384;
        const float* W = (mm == 0) ? Wq : (mm == 1) ? Wk : (mm == 2) ? Wv : Ws;
        shW[mm][r] = W[r];
    }
    if (tid < 24) {
        int mm = tid / 6, cc = tid % 6;
        const float* b = (mm == 0) ? bq : (mm == 1) ? bk : (mm == 2) ? bv : bs;
        shB[mm][cc] = b[cc];
    }
    int base = blk * 8 * 64;
#pragma unroll
    for (int r = 0; r < 2; r++) {
        int i = tid + r * 256;
        int node = blk * 8 + (i >> 6);
        shH[i >> 6][i & 63] = (node < n) ? g_h[base + i] : 0.f;
    }
    __syncthreads();

    int w = tid >> 5;
    int lane = tid & 31;
    int node = blk * 8 + w;
    if (node >= n || lane >= 24) return;
    int mm = lane / 6, cc = lane % 6;
    float acc = shB[mm][cc];
#pragma unroll
    for (int k = 0; k < 64; k++) acc += shH[w][k] * shW[mm][k * 6 + cc];
    if (mm == 0)      g_qs[node * 16 + cc]     = acc * 0.4082482904638631f;
    else if (mm == 1) g_kv[node * 16 + cc]     = acc;
    else if (mm == 2) g_kv[node * 16 + 6 + cc] = acc;
    else              g_qs[node * 16 + 8 + cc] = acc;
}

// ---------------- fused attention layer 2 (single-pass online softmax) ----------------
__global__ void k_attn2(int n) {
    int warp = (blockIdx.x * blockDim.x + threadIdx.x) >> 5;
    int lane = threadIdx.x & 31;
    if (warp >= n) return;
    int t = warp;

    float q[6];
#pragma unroll
    for (int j = 0; j < 6; j++) q[j] = g_qs[t * 16 + j];   // pre-scaled

    const float4* kv4 = reinterpret_cast<const float4*>(g_kv);
    int beg = g_rowptr[t], end = g_rowptr[t + 1];

    float m = -INFINITY, den = 0.f;
    float acc[6] = {0.f, 0.f, 0.f, 0.f, 0.f, 0.f};

    for (int i = beg + lane; i < end; i += 32) {
        int s = g_csrsrc[i];
        float4 f0 = kv4[s * 4 + 0];
        float4 f1 = kv4[s * 4 + 1];
        float4 f2 = kv4[s * 4 + 2];
        float l = q[0] * f0.x + q[1] * f0.y + q[2] * f0.z + q[3] * f0.w
                + q[4] * f1.x + q[5] * f1.y;
        float mn = fmaxf(m, l);
        float sc = __expf(m - mn);   // m=-inf -> 0
        float w  = __expf(l - mn);
        den = den * sc + w;
        acc[0] = acc[0] * sc + w * f1.z;
        acc[1] = acc[1] * sc + w * f1.w;
        acc[2] = acc[2] * sc + w * f2.x;
        acc[3] = acc[3] * sc + w * f2.y;
        acc[4] = acc[4] * sc + w * f2.z;
        acc[5] = acc[5] * sc + w * f2.w;
        m = mn;
    }

    // guarded butterfly merge
#pragma unroll
    for (int off = 16; off > 0; off >>= 1) {
        float m2   = __shfl_xor_sync(0xFFFFFFFFu, m,   off);
        float den2 = __shfl_xor_sync(0xFFFFFFFFu, den, off);
        float t0 = __shfl_xor_sync(0xFFFFFFFFu, acc[0], off);
        float t1 = __shfl_xor_sync(0xFFFFFFFFu, acc[1], off);
        float t2 = __shfl_xor_sync(0xFFFFFFFFu, acc[2], off);
        float t3 = __shfl_xor_sync(0xFFFFFFFFu, acc[3], off);
        float t4 = __shfl_xor_sync(0xFFFFFFFFu, acc[4], off);
        float t5 = __shfl_xor_sync(0xFFFFFFFFu, acc[5], off);
        float mn = fmaxf(m, m2);
        float sa = (den  > 0.f) ? __expf(m  - mn) : 0.f;
        float sb = (den2 > 0.f) ? __expf(m2 - mn) : 0.f;
        den = den * sa + den2 * sb;
        acc[0] = acc[0] * sa + t0 * sb;
        acc[1] = acc[1] * sa + t1 * sb;
        acc[2] = acc[2] * sa + t2 * sb;
        acc[3] = acc[3] * sa + t3 * sb;
        acc[4] = acc[4] * sa + t4 * sb;
        acc[5] = acc[5] * sa + t5 * sb;
        m = mn;
    }

    if (lane == 0) {
        float inv = 1.f / (den + 1e-16f);
#pragma unroll
        for (int j = 0; j < 6; j++)
            g_o2[t * 6 + j] = acc[j] * inv + g_qs[t * 16 + 8 + j];
    }
}

// ---------------- pooling + output ----------------
__global__ void k_pool(const int* __restrict__ batch, int n) {
    __shared__ float ssum[GG * 6];
    __shared__ float scnt[GG];
    __shared__ int   sflag[GG];
    int tid = threadIdx.x;
    for (int i = tid; i < GG * 6; i += blockDim.x) ssum[i] = 0.f;
    for (int i = tid; i < GG; i += blockDim.x) { scnt[i] = 0.f; sflag[i] = 0; }
    __syncthreads();

    int node = blockIdx.x * blockDim.x + tid;
    if (node < n) {
        int g = __ldg(&batch[node]);
#pragma unroll
        for (int c = 0; c < 6; c++)
            atomicAdd(&ssum[g * 6 + c], g_o2[node * 6 + c]);
        atomicAdd(&scnt[g], 1.f);
        sflag[g] = 1;
    }
    __syncthreads();
    for (int g = tid; g < GG; g += blockDim.x) {
        if (sflag[g]) {
            atomicAdd(&g_cnt[g], scnt[g]);
#pragma unroll
            for (int c = 0; c < 6; c++)
                atomicAdd(&g_sums[g * 6 + c], ssum[g * 6 + c]);
        }
    }
}

__global__ void k_out(float* __restrict__ out) {
    int g = threadIdx.x;
    if (g >= GG) return;
    float cnt = fmaxf(g_cnt[g], 1.f);
    float p[6];
    float m = -INFINITY;
#pragma unroll
    for (int c = 0; c < 6; c++) { p[c] = g_sums[g * 6 + c] / cnt; m = fmaxf(m, p[c]); }
    float s = 0.f;
#pragma unroll
    for (int c = 0; c < 6; c++) s += expf(p[c] - m);
    float lse = m + logf(s);
#pragma unroll
    for (int c = 0; c < 6; c++) out[g * 6 + c] = p[c] - lse;
}

// ---------------- launch ----------------
extern "C" void kernel_launch(void* const* d_in, const int* in_sizes, int n_in,
                              void* d_out, int out_size) {
    const float* x    = (const float*)d_in[0];
    const int*   ei   = (const int*)  d_in[1];
    const int*   batch= (const int*)  d_in[2];
    const float* Wq1  = (const float*)d_in[3];
    const float* bq1  = (const float*)d_in[4];
    const float* Wk1  = (const float*)d_in[5];
    const float* bk1  = (const float*)d_in[6];
    const float* Wv1  = (const float*)d_in[7];
    const float* bv1  = (const float*)d_in[8];
    const float* Ws1  = (const float*)d_in[9];
    const float* bs1  = (const float*)d_in[10];
    const float* Wq2  = (const float*)d_in[11];
    const float* bq2  = (const float*)d_in[12];
    const float* Wk2  = (const float*)d_in[13];
    const float* bk2  = (const float*)d_in[14];
    const float* Wv2  = (const float*)d_in[15];
    const float* bv2  = (const float*)d_in[16];
    const float* Ws2  = (const float*)d_in[17];
    const float* bs2  = (const float*)d_in[18];
    float* out = (float*)d_out;

    int N = in_sizes[0] / 3;
    int E = in_sizes[1] / 2;
    const int* src = ei;
    const int* dst = ei + E;

    const int B = 256;
    int NB = (N + 1023) / 1024;   // scan blocks (<=128)

    k_prep<<<(N * 4 + B - 1) / B, B>>>(x, Wq1, bq1, Wk1, bk1, N);
    k_hist<<<(E + B - 1) / B, B>>>(dst, E);
    k_scan_blk<<<NB, 1024>>>(N);
    k_scan_top<<<1, 32>>>(NB);
    k_scan_wr<<<NB, 1024>>>(N, E);
    k_scatter<<<(E + B - 1) / B, B>>>(src, dst, E);
    k_attn1<<<(N * 32 + B - 1) / B, B>>>(Wv1, bv1, Ws1, bs1, N);
    k_gemm2<<<(N + 7) / 8, B>>>(Wq2, bq2, Wk2, bk2, Wv2, bv2, Ws2, bs2, N);
    k_attn2<<<(N * 32 + B - 1) / B, B>>>(N);
    k_pool<<<(N + B - 1) / B, B>>>(batch, N);
    k_out<<<1, 64>>>(out);
}

// round 7
// speedup vs baseline: 4.8449x; 1.1431x over previous
#include <cuda_runtime.h>
#include <math.h>

#define NN 100000
#define EE 3200000
#define GG 64

// ---------------- static device scratch ----------------
__device__ float4 g_x4[NN];          // padded x
__device__ float4 g_cf[NN * 4];      // per (node,head): (e0,e1,e2,d0)
__device__ float  g_h [NN * 64];

__device__ float g_kv[NN * 16];      // [0..5]=k2, [6..11]=v2, pad to 64B
__device__ float g_qs[NN * 16];      // [0..5]=q2 (pre-scaled), [8..13]=s2
__device__ float g_o2[NN * 6];

__device__ int g_deg   [NN];
__device__ int g_rowptr[NN + 1];
__device__ int g_cursor[NN];
__device__ int g_csrsrc[EE];
__device__ int g_bsum[128];
__device__ int g_boff[128];

__device__ float g_sums[GG * 6];
__device__ float g_cnt [GG];

// ---------------- fused prep: zero + x4 + coef ----------------
__global__ void k_prep(const float* __restrict__ x,
                       const float* __restrict__ Wq, const float* __restrict__ bq,
                       const float* __restrict__ Wk, const float* __restrict__ bk,
                       int n) {
    int idx = blockIdx.x * blockDim.x + threadIdx.x;
    if (idx < GG * 6) g_sums[idx] = 0.f;
    if (idx < GG) g_cnt[idx] = 0.f;
    if (idx >= n * 4) return;
    int node = idx >> 2, h = idx & 3;
    float x0 = __ldg(&x[node * 3 + 0]);
    float x1 = __ldg(&x[node * 3 + 1]);
    float x2 = __ldg(&x[node * 3 + 2]);
    if (h == 0) {
        g_deg[node] = 0;
        g_x4[node] = make_float4(x0, x1, x2, 0.f);
    }
    float d0 = 0.f, e0 = 0.f, e1 = 0.f, e2 = 0.f;
    int base = h * 16;
#pragma unroll
    for (int c = 0; c < 16; c++) {
        int cc = base + c;
        float qc = bq[cc] + x0 * Wq[cc] + x1 * Wq[64 + cc] + x2 * Wq[128 + cc];
        d0 += qc * bk[cc];
        e0 += qc * Wk[cc];
        e1 += qc * Wk[64 + cc];
        e2 += qc * Wk[128 + cc];
    }
    // pre-scale by 1/sqrt(16) so logit = d0 + e.x directly
    g_cf[idx] = make_float4(e0 * 0.25f, e1 * 0.25f, e2 * 0.25f, d0 * 0.25f);
}

// ---------------- CSR build ----------------
__global__ void k_hist(const int* __restrict__ dst, int e) {
    int i = blockIdx.x * blockDim.x + threadIdx.x;
    if (i < e) atomicAdd(&g_deg[dst[i]], 1);
}

__global__ void k_scan_blk(int n) {
    __shared__ int wsum[32];
    int i = blockIdx.x * 1024 + threadIdx.x;
    int v = (i < n) ? g_deg[i] : 0;
#pragma unroll
    for (int off = 16; off > 0; off >>= 1)
        v += __shfl_xor_sync(0xFFFFFFFFu, v, off);
    int lane = threadIdx.x & 31, wid = threadIdx.x >> 5;
    if (lane == 0) wsum[wid] = v;
    __syncthreads();
    if (wid == 0) {
        int s = wsum[lane];
#pragma unroll
        for (int off = 16; off > 0; off >>= 1)
            s += __shfl_xor_sync(0xFFFFFFFFu, s, off);
        if (lane == 0) g_bsum[blockIdx.x] = s;
    }
}

__global__ void k_scan_top(int nb) {
    if (threadIdx.x == 0) {
        int run = 0;
        for (int b = 0; b < nb; b++) {
            int t = g_bsum[b];
            g_boff[b] = run;
            run += t;
        }
    }
}

__global__ void k_scan_wr(int n, int e) {
    __shared__ int wsum[32];
    int i = blockIdx.x * 1024 + threadIdx.x;
    int v = (i < n) ? g_deg[i] : 0;
    int lane = threadIdx.x & 31, wid = threadIdx.x >> 5;
    int x = v;
#pragma unroll
    for (int off = 1; off < 32; off <<= 1) {
        int y = __shfl_up_sync(0xFFFFFFFFu, x, off);
        if (lane >= off) x += y;
    }
    if (lane == 31) wsum[wid] = x;
    __syncthreads();
    if (wid == 0) {
        int w = wsum[lane];
#pragma unroll
        for (int off = 1; off < 32; off <<= 1) {
            int y = __shfl_up_sync(0xFFFFFFFFu, w, off);
            if (lane >= off) w += y;
        }
        wsum[lane] = w;
    }
    __syncthreads();
    int excl = x - v + ((wid > 0) ? wsum[wid - 1] : 0) + g_boff[blockIdx.x];
    if (i < n) { g_rowptr[i] = excl; g_cursor[i] = excl; }
    if (i == n) g_rowptr[n] = e;
}

__global__ void k_scatter(const int* __restrict__ src, const int* __restrict__ dst, int e) {
    int i = blockIdx.x * blockDim.x + threadIdx.x;
    if (i >= e) return;
    int p = atomicAdd(&g_cursor[dst[i]], 1);
    g_csrsrc[p] = src[i];
}

// ---------------- fused attention layer 1 (no-max softmax; exact in num/den) ----------------
__global__ void k_attn1(const float* __restrict__ Wv, const float* __restrict__ bv,
                        const float* __restrict__ Ws, const float* __restrict__ bs,
                        int n) {
    int warp = (blockIdx.x * blockDim.x + threadIdx.x) >> 5;
    int lane = threadIdx.x & 31;
    if (warp >= n) return;
    int t = warp;

    float4 cf0 = g_cf[t * 4 + 0];
    float4 cf1 = g_cf[t * 4 + 1];
    float4 cf2 = g_cf[t * 4 + 2];
    float4 cf3 = g_cf[t * 4 + 3];
    int beg = g_rowptr[t], end = g_rowptr[t + 1];

    float d0 = 0.f, d1 = 0.f, d2 = 0.f, d3 = 0.f;
    float a00 = 0.f, a01 = 0.f, a02 = 0.f;
    float a10 = 0.f, a11 = 0.f, a12 = 0.f;
    float a20 = 0.f, a21 = 0.f, a22 = 0.f;
    float a30 = 0.f, a31 = 0.f, a32 = 0.f;

    for (int i = beg + lane; i < end; i += 32) {
        int s = g_csrsrc[i];
        float4 xs = g_x4[s];
        float w0 = __expf(cf0.w + cf0.x * xs.x + cf0.y * xs.y + cf0.z * xs.z);
        float w1 = __expf(cf1.w + cf1.x * xs.x + cf1.y * xs.y + cf1.z * xs.z);
        float w2 = __expf(cf2.w + cf2.x * xs.x + cf2.y * xs.y + cf2.z * xs.z);
        float w3 = __expf(cf3.w + cf3.x * xs.x + cf3.y * xs.y + cf3.z * xs.z);
        d0 += w0; a00 += w0 * xs.x; a01 += w0 * xs.y; a02 += w0 * xs.z;
        d1 += w1; a10 += w1 * xs.x; a11 += w1 * xs.y; a12 += w1 * xs.z;
        d2 += w2; a20 += w2 * xs.x; a21 += w2 * xs.y; a22 += w2 * xs.z;
        d3 += w3; a30 += w3 * xs.x; a31 += w3 * xs.y; a32 += w3 * xs.z;
    }

    // plain butterfly sums
#pragma unroll
    for (int off = 16; off > 0; off >>= 1) {
        d0 += __shfl_xor_sync(0xFFFFFFFFu, d0, off);
        d1 += __shfl_xor_sync(0xFFFFFFFFu, d1, off);
        d2 += __shfl_xor_sync(0xFFFFFFFFu, d2, off);
        d3 += __shfl_xor_sync(0xFFFFFFFFu, d3, off);
        a00 += __shfl_xor_sync(0xFFFFFFFFu, a00, off);
        a01 += __shfl_xor_sync(0xFFFFFFFFu, a01, off);
        a02 += __shfl_xor_sync(0xFFFFFFFFu, a02, off);
        a10 += __shfl_xor_sync(0xFFFFFFFFu, a10, off);
        a11 += __shfl_xor_sync(0xFFFFFFFFu, a11, off);
        a12 += __shfl_xor_sync(0xFFFFFFFFu, a12, off);
        a20 += __shfl_xor_sync(0xFFFFFFFFu, a20, off);
        a21 += __shfl_xor_sync(0xFFFFFFFFu, a21, off);
        a22 += __shfl_xor_sync(0xFFFFFFFFu, a22, off);
        a30 += __shfl_xor_sync(0xFFFFFFFFu, a30, off);
        a31 += __shfl_xor_sync(0xFFFFFFFFu, a31, off);
        a32 += __shfl_xor_sync(0xFFFFFFFFu, a32, off);
    }

    // epilogue: lane owns dims c, c+1; head = lane/8
    int c = lane * 2;
    int h = lane >> 3;
    float denh = (h == 0) ? d0 : (h == 1) ? d1 : (h == 2) ? d2 : d3;
    float sxa  = (h == 0) ? a00 : (h == 1) ? a10 : (h == 2) ? a20 : a30;
    float sxb  = (h == 0) ? a01 : (h == 1) ? a11 : (h == 2) ? a21 : a31;
    float sxc  = (h == 0) ? a02 : (h == 1) ? a12 : (h == 2) ? a22 : a32;
    float inv = 1.f / (denh + 1e-16f);

    float4 xt = g_x4[t];
    float o[2];
#pragma unroll
    for (int k = 0; k < 2; k++) {
        int cc = c + k;
        float num = bv[cc] * denh + Wv[cc] * sxa + Wv[64 + cc] * sxb + Wv[128 + cc] * sxc;
        float val = num * inv + bs[cc] + xt.x * Ws[cc] + xt.y * Ws[64 + cc] + xt.z * Ws[128 + cc];
        o[k] = fmaxf(val, 0.f);
    }
    *reinterpret_cast<float2*>(g_h + t * 64 + c) = make_float2(o[0], o[1]);
}

// ---------------- layer 2 projection ----------------
__global__ void k_gemm2(const float* __restrict__ Wq, const float* __restrict__ bq,
                        const float* __restrict__ Wk, const float* __restrict__ bk,
                        const float* __restrict__ Wv, const float* __restrict__ bv,
                        const float* __restrict__ Ws, const float* __restrict__ bs,
                        int n) {
    __shared__ float shH[8][64];
    __shared__ float shW[4][390];
    __shared__ float shB[4][6];
    int tid = threadIdx.x;
    int blk = blockIdx.x;

    for (int i = tid; i < 384 * 4; i += 256) {
        int mm = i / 384, r = i % 384;
        const float* W = (mm == 0) ? Wq : (mm == 1) ? Wk : (mm == 2) ? Wv : Ws;
        shW[mm][r] = W[r];
    }
    if (tid < 24) {
        int mm = tid / 6, cc = tid % 6;
        const float* b = (mm == 0) ? bq : (mm == 1) ? bk : (mm == 2) ? bv : bs;
        shB[mm][cc] = b[cc];
    }
    int base = blk * 8 * 64;
#pragma unroll
    for (int r = 0; r < 2; r++) {
        int i = tid + r * 256;
        int node = blk * 8 + (i >> 6);
        shH[i >> 6][i & 63] = (node < n) ? g_h[base + i] : 0.f;
    }
    __syncthreads();

    int w = tid >> 5;
    int lane = tid & 31;
    int node = blk * 8 + w;
    if (node >= n || lane >= 24) return;
    int mm = lane / 6, cc = lane % 6;
    float acc = shB[mm][cc];
#pragma unroll
    for (int k = 0; k < 64; k++) acc += shH[w][k] * shW[mm][k * 6 + cc];
    if (mm == 0)      g_qs[node * 16 + cc]     = acc * 0.4082482904638631f;
    else if (mm == 1) g_kv[node * 16 + cc]     = acc;
    else if (mm == 2) g_kv[node * 16 + 6 + cc] = acc;
    else              g_qs[node * 16 + 8 + cc] = acc;
}

// ---------------- fused attention layer 2 (no-max softmax) ----------------
__global__ void k_attn2(int n) {
    int warp = (blockIdx.x * blockDim.x + threadIdx.x) >> 5;
    int lane = threadIdx.x & 31;
    if (warp >= n) return;
    int t = warp;

    float q[6];
#pragma unroll
    for (int j = 0; j < 6; j++) q[j] = g_qs[t * 16 + j];   // pre-scaled

    const float4* kv4 = reinterpret_cast<const float4*>(g_kv);
    int beg = g_rowptr[t], end = g_rowptr[t + 1];

    float den = 0.f;
    float acc[6] = {0.f, 0.f, 0.f, 0.f, 0.f, 0.f};

    for (int i = beg + lane; i < end; i += 32) {
        int s = g_csrsrc[i];
        float4 f0 = kv4[s * 4 + 0];
        float4 f1 = kv4[s * 4 + 1];
        float4 f2 = kv4[s * 4 + 2];
        float l = q[0] * f0.x + q[1] * f0.y + q[2] * f0.z + q[3] * f0.w
                + q[4] * f1.x + q[5] * f1.y;
        float w = __expf(l);
        den += w;
        acc[0] += w * f1.z;
        acc[1] += w * f1.w;
        acc[2] += w * f2.x;
        acc[3] += w * f2.y;
        acc[4] += w * f2.z;
        acc[5] += w * f2.w;
    }

#pragma unroll
    for (int off = 16; off > 0; off >>= 1) {
        den += __shfl_xor_sync(0xFFFFFFFFu, den, off);
        acc[0] += __shfl_xor_sync(0xFFFFFFFFu, acc[0], off);
        acc[1] += __shfl_xor_sync(0xFFFFFFFFu, acc[1], off);
        acc[2] += __shfl_xor_sync(0xFFFFFFFFu, acc[2], off);
        acc[3] += __shfl_xor_sync(0xFFFFFFFFu, acc[3], off);
        acc[4] += __shfl_xor_sync(0xFFFFFFFFu, acc[4], off);
        acc[5] += __shfl_xor_sync(0xFFFFFFFFu, acc[5], off);
    }

    if (lane == 0) {
        float inv = 1.f / (den + 1e-16f);
#pragma unroll
        for (int j = 0; j < 6; j++)
            g_o2[t * 6 + j] = acc[j] * inv + g_qs[t * 16 + 8 + j];
    }
}

// ---------------- pooling + output ----------------
__global__ void k_pool(const int* __restrict__ batch, int n) {
    __shared__ float ssum[GG * 6];
    __shared__ float scnt[GG];
    __shared__ int   sflag[GG];
    int tid = threadIdx.x;
    for (int i = tid; i < GG * 6; i += blockDim.x) ssum[i] = 0.f;
    for (int i = tid; i < GG; i += blockDim.x) { scnt[i] = 0.f; sflag[i] = 0; }
    __syncthreads();

    int node = blockIdx.x * blockDim.x + tid;
    if (node < n) {
        int g = __ldg(&batch[node]);
#pragma unroll
        for (int c = 0; c < 6; c++)
            atomicAdd(&ssum[g * 6 + c], g_o2[node * 6 + c]);
        atomicAdd(&scnt[g], 1.f);
        sflag[g] = 1;
    }
    __syncthreads();
    for (int g = tid; g < GG; g += blockDim.x) {
        if (sflag[g]) {
            atomicAdd(&g_cnt[g], scnt[g]);
#pragma unroll
            for (int c = 0; c < 6; c++)
                atomicAdd(&g_sums[g * 6 + c], ssum[g * 6 + c]);
        }
    }
}

__global__ void k_out(float* __restrict__ out) {
    int g = threadIdx.x;
    if (g >= GG) return;
    float cnt = fmaxf(g_cnt[g], 1.f);
    float p[6];
    float m = -INFINITY;
#pragma unroll
    for (int c = 0; c < 6; c++) { p[c] = g_sums[g * 6 + c] / cnt; m = fmaxf(m, p[c]); }
    float s = 0.f;
#pragma unroll
    for (int c = 0; c < 6; c++) s += expf(p[c] - m);
    float lse = m + logf(s);
#pragma unroll
    for (int c = 0; c < 6; c++) out[g * 6 + c] = p[c] - lse;
}

// ---------------- launch ----------------
extern "C" void kernel_launch(void* const* d_in, const int* in_sizes, int n_in,
                              void* d_out, int out_size) {
    const float* x    = (const float*)d_in[0];
    const int*   ei   = (const int*)  d_in[1];
    const int*   batch= (const int*)  d_in[2];
    const float* Wq1  = (const float*)d_in[3];
    const float* bq1  = (const float*)d_in[4];
    const float* Wk1  = (const float*)d_in[5];
    const float* bk1  = (const float*)d_in[6];
    const float* Wv1  = (const float*)d_in[7];
    const float* bv1  = (const float*)d_in[8];
    const float* Ws1  = (const float*)d_in[9];
    const float* bs1  = (const float*)d_in[10];
    const float* Wq2  = (const float*)d_in[11];
    const float* bq2  = (const float*)d_in[12];
    const float* Wk2  = (const float*)d_in[13];
    const float* bk2  = (const float*)d_in[14];
    const float* Wv2  = (const float*)d_in[15];
    const float* bv2  = (const float*)d_in[16];
    const float* Ws2  = (const float*)d_in[17];
    const float* bs2  = (const float*)d_in[18];
    float* out = (float*)d_out;

    int N = in_sizes[0] / 3;
    int E = in_sizes[1] / 2;
    const int* src = ei;
    const int* dst = ei + E;

    const int B = 256;
    int NB = (N + 1023) / 1024;

    k_prep<<<(N * 4 + B - 1) / B, B>>>(x, Wq1, bq1, Wk1, bk1, N);
    k_hist<<<(E + B - 1) / B, B>>>(dst, E);
    k_scan_blk<<<NB, 1024>>>(N);
    k_scan_top<<<1, 32>>>(NB);
    k_scan_wr<<<NB, 1024>>>(N, E);
    k_scatter<<<(E + B - 1) / B, B>>>(src, dst, E);
    k_attn1<<<(N * 32 + B - 1) / B, B>>>(Wv1, bv1, Ws1, bs1, N);
    k_gemm2<<<(N + 7) / 8, B>>>(Wq2, bq2, Wk2, bk2, Wv2, bv2, Ws2, bs2, N);
    k_attn2<<<(N * 32 + B - 1) / B, B>>>(N);
    k_pool<<<(N + B - 1) / B, B>>>(batch, N);
    k_out<<<1, 64>>>(out);
}

// round 8
// speedup vs baseline: 5.9079x; 1.2194x over previous
#include <cuda_runtime.h>
#include <math.h>

#define NN 100000
#define EE 3200000
#define GG 64

// ---------------- static device scratch ----------------
__device__ float4 g_x4[NN];          // padded x
__device__ float4 g_cf[NN * 4];      // per (node,head): (e0,e1,e2,d0) pre-scaled
__device__ float4 g_ds[NN * 4];      // per (node,head): (den, sx0, sx1, sx2)

__device__ float  g_kv[NN * 16];     // [0..5]=k2, [6..11]=v2, pad to 64B
__device__ float  g_qs[NN * 16];     // [0..5]=q2 (pre-scaled), [8..13]=s2
__device__ float4 g_o2p[NN * 2];     // padded layer-2 output (6 used)

__device__ int g_deg   [NN];
__device__ int g_rowptr[NN + 1];
__device__ int g_cursor[NN];
__device__ int g_csrsrc[EE];
__device__ int g_bsum[128];

__device__ float g_sums[GG * 6];
__device__ float g_cnt [GG];

// ---------------- fused prep: zero + x4 + coef ----------------
__global__ void k_prep(const float* __restrict__ x,
                       const float* __restrict__ Wq, const float* __restrict__ bq,
                       const float* __restrict__ Wk, const float* __restrict__ bk,
                       int n) {
    int idx = blockIdx.x * blockDim.x + threadIdx.x;
    if (idx < GG * 6) g_sums[idx] = 0.f;
    if (idx < GG) g_cnt[idx] = 0.f;
    if (idx >= n * 4) return;
    int node = idx >> 2, h = idx & 3;
    float x0 = __ldg(&x[node * 3 + 0]);
    float x1 = __ldg(&x[node * 3 + 1]);
    float x2 = __ldg(&x[node * 3 + 2]);
    if (h == 0) {
        g_deg[node] = 0;
        g_x4[node] = make_float4(x0, x1, x2, 0.f);
    }
    float d0 = 0.f, e0 = 0.f, e1 = 0.f, e2 = 0.f;
    int base = h * 16;
#pragma unroll
    for (int c = 0; c < 16; c++) {
        int cc = base + c;
        float qc = bq[cc] + x0 * Wq[cc] + x1 * Wq[64 + cc] + x2 * Wq[128 + cc];
        d0 += qc * bk[cc];
        e0 += qc * Wk[cc];
        e1 += qc * Wk[64 + cc];
        e2 += qc * Wk[128 + cc];
    }
    g_cf[idx] = make_float4(e0 * 0.25f, e1 * 0.25f, e2 * 0.25f, d0 * 0.25f);
}

// ---------------- CSR build ----------------
__global__ void k_hist(const int* __restrict__ dst, int e) {
    int i = blockIdx.x * blockDim.x + threadIdx.x;
    if (i < e) atomicAdd(&g_deg[dst[i]], 1);
}

__global__ void k_scan_blk(int n) {
    __shared__ int wsum[32];
    int i = blockIdx.x * 1024 + threadIdx.x;
    int v = (i < n) ? g_deg[i] : 0;
#pragma unroll
    for (int off = 16; off > 0; off >>= 1)
        v += __shfl_xor_sync(0xFFFFFFFFu, v, off);
    int lane = threadIdx.x & 31, wid = threadIdx.x >> 5;
    if (lane == 0) wsum[wid] = v;
    __syncthreads();
    if (wid == 0) {
        int s = wsum[lane];
#pragma unroll
        for (int off = 16; off > 0; off >>= 1)
            s += __shfl_xor_sync(0xFFFFFFFFu, s, off);
        if (lane == 0) g_bsum[blockIdx.x] = s;
    }
}

// scan_wr with inlined top-level scan (each block redundantly sums prior block sums)
__global__ void k_scan_wr(int n, int e, int nb) {
    __shared__ int wsum[32];
    __shared__ int sboff;
    int lane = threadIdx.x & 31, wid = threadIdx.x >> 5;

    if (wid == 0) {
        int acc = 0;
        for (int j = lane; j < nb; j += 32)
            acc += (j < blockIdx.x) ? g_bsum[j] : 0;
#pragma unroll
        for (int off = 16; off > 0; off >>= 1)
            acc += __shfl_xor_sync(0xFFFFFFFFu, acc, off);
        if (lane == 0) sboff = acc;
    }

    int i = blockIdx.x * 1024 + threadIdx.x;
    int v = (i < n) ? g_deg[i] : 0;
    int x = v;
#pragma unroll
    for (int off = 1; off < 32; off <<= 1) {
        int y = __shfl_up_sync(0xFFFFFFFFu, x, off);
        if (lane >= off) x += y;
    }
    if (lane == 31) wsum[wid] = x;
    __syncthreads();
    if (wid == 0) {
        int w = wsum[lane];
#pragma unroll
        for (int off = 1; off < 32; off <<= 1) {
            int y = __shfl_up_sync(0xFFFFFFFFu, w, off);
            if (lane >= off) w += y;
        }
        wsum[lane] = w;
    }
    __syncthreads();
    int excl = x - v + ((wid > 0) ? wsum[wid - 1] : 0) + sboff;
    if (i < n) { g_rowptr[i] = excl; g_cursor[i] = excl; }
    if (i == n) g_rowptr[n] = e;
}

__global__ void k_scatter(const int* __restrict__ src, const int* __restrict__ dst, int e) {
    int i = blockIdx.x * blockDim.x + threadIdx.x;
    if (i >= e) return;
    int p = atomicAdd(&g_cursor[dst[i]], 1);
    g_csrsrc[p] = src[i];
}

// ---------------- attention layer 1: thread per node, no reductions ----------------
__global__ void k_attn1(int n) {
    int t = blockIdx.x * blockDim.x + threadIdx.x;
    if (t >= n) return;

    float4 cf0 = g_cf[t * 4 + 0];
    float4 cf1 = g_cf[t * 4 + 1];
    float4 cf2 = g_cf[t * 4 + 2];
    float4 cf3 = g_cf[t * 4 + 3];
    int beg = g_rowptr[t], end = g_rowptr[t + 1];

    float4 ds0 = make_float4(0.f, 0.f, 0.f, 0.f);
    float4 ds1 = make_float4(0.f, 0.f, 0.f, 0.f);
    float4 ds2 = make_float4(0.f, 0.f, 0.f, 0.f);
    float4 ds3 = make_float4(0.f, 0.f, 0.f, 0.f);

    for (int i = beg; i < end; i++) {
        int s = g_csrsrc[i];
        float4 xs = g_x4[s];
        float w0 = __expf(cf0.w + cf0.x * xs.x + cf0.y * xs.y + cf0.z * xs.z);
        float w1 = __expf(cf1.w + cf1.x * xs.x + cf1.y * xs.y + cf1.z * xs.z);
        float w2 = __expf(cf2.w + cf2.x * xs.x + cf2.y * xs.y + cf2.z * xs.z);
        float w3 = __expf(cf3.w + cf3.x * xs.x + cf3.y * xs.y + cf3.z * xs.z);
        ds0.x += w0; ds0.y += w0 * xs.x; ds0.z += w0 * xs.y; ds0.w += w0 * xs.z;
        ds1.x += w1; ds1.y += w1 * xs.x; ds1.z += w1 * xs.y; ds1.w += w1 * xs.z;
        ds2.x += w2; ds2.y += w2 * xs.x; ds2.z += w2 * xs.y; ds2.w += w2 * xs.z;
        ds3.x += w3; ds3.y += w3 * xs.x; ds3.z += w3 * xs.y; ds3.w += w3 * xs.z;
    }
    g_ds[t * 4 + 0] = ds0;
    g_ds[t * 4 + 1] = ds1;
    g_ds[t * 4 + 2] = ds2;
    g_ds[t * 4 + 3] = ds3;
}

// ---------------- layer 2 projection (with fused layer-1 epilogue) ----------------
// 8 nodes per 256-thread block: reconstruct h in shared from g_ds + x + (Wv,bv,Ws,bs),
// then project to q2/k2/v2/s2.
__global__ void k_gemm2(const float* __restrict__ Wv1, const float* __restrict__ bv1,
                        const float* __restrict__ Ws1, const float* __restrict__ bs1,
                        const float* __restrict__ Wq, const float* __restrict__ bq,
                        const float* __restrict__ Wk, const float* __restrict__ bk,
                        const float* __restrict__ Wv, const float* __restrict__ bv,
                        const float* __restrict__ Ws, const float* __restrict__ bs,
                        int n) {
    __shared__ float  shH[8][64];
    __shared__ float  shW2[4][390];    // layer-2 weights (384 used, padded)
    __shared__ float  shB2[4][6];
    __shared__ float  shWv[192], shBv[64], shWs[192], shBs[64];
    __shared__ float4 shDS[32];        // 8 nodes x 4 heads
    __shared__ float4 shX[8];
    int tid = threadIdx.x;
    int blk = blockIdx.x;

    // stage layer-2 weights
    for (int i = tid; i < 384 * 4; i += 256) {
        int mm = i / 384, r = i % 384;
        const float* W = (mm == 0) ? Wq : (mm == 1) ? Wk : (mm == 2) ? Wv : Ws;
        shW2[mm][r] = W[r];
    }
    if (tid < 24) {
        int mm = tid / 6, cc = tid % 6;
        const float* b = (mm == 0) ? bq : (mm == 1) ? bk : (mm == 2) ? bv : bs;
        shB2[mm][cc] = b[cc];
    }
    // stage layer-1 epilogue weights
    if (tid < 192) { shWv[tid] = Wv1[tid]; shWs[tid] = Ws1[tid]; }
    else if (tid < 256) { shBv[tid - 192] = bv1[tid - 192]; shBs[tid - 192] = bs1[tid - 192]; }
    // stage per-node data
    if (tid < 32) {
        int gidx = blk * 32 + tid;
        shDS[tid] = (gidx < n * 4) ? g_ds[gidx] : make_float4(0.f, 0.f, 0.f, 0.f);
    }
    if (tid < 8) {
        int node = blk * 8 + tid;
        shX[tid] = (node < n) ? g_x4[node] : make_float4(0.f, 0.f, 0.f, 0.f);
    }
    __syncthreads();

    // reconstruct h (2 values per thread)
#pragma unroll
    for (int r = 0; r < 2; r++) {
        int idx = tid + r * 256;
        int local = idx >> 6, c = idx & 63;
        float4 ds = shDS[local * 4 + (c >> 4)];
        float4 xt = shX[local];
        float num = shBv[c] * ds.x + shWv[c] * ds.y + shWv[64 + c] * ds.z + shWv[128 + c] * ds.w;
        float val = num / (ds.x + 1e-16f)
                  + shBs[c] + xt.x * shWs[c] + xt.y * shWs[64 + c] + xt.z * shWs[128 + c];
        shH[local][c] = fmaxf(val, 0.f);
    }
    __syncthreads();

    int w = tid >> 5;
    int lane = tid & 31;
    int node = blk * 8 + w;
    if (node >= n || lane >= 24) return;
    int mm = lane / 6, cc = lane % 6;
    float acc = shB2[mm][cc];
#pragma unroll
    for (int k = 0; k < 64; k++) acc += shH[w][k] * shW2[mm][k * 6 + cc];
    if (mm == 0)      g_qs[node * 16 + cc]     = acc * 0.4082482904638631f;
    else if (mm == 1) g_kv[node * 16 + cc]     = acc;
    else if (mm == 2) g_kv[node * 16 + 6 + cc] = acc;
    else              g_qs[node * 16 + 8 + cc] = acc;
}

// ---------------- attention layer 2: thread per node ----------------
__global__ void k_attn2(int n) {
    int t = blockIdx.x * blockDim.x + threadIdx.x;
    if (t >= n) return;

    float4 qa = *reinterpret_cast<const float4*>(g_qs + t * 16);
    float2 qb = *reinterpret_cast<const float2*>(g_qs + t * 16 + 4);

    const float4* kv4 = reinterpret_cast<const float4*>(g_kv);
    int beg = g_rowptr[t], end = g_rowptr[t + 1];

    float den = 0.f;
    float a0 = 0.f, a1 = 0.f, a2 = 0.f, a3 = 0.f, a4 = 0.f, a5 = 0.f;

    for (int i = beg; i < end; i++) {
        int s = g_csrsrc[i];
        float4 f0 = kv4[s * 4 + 0];
        float4 f1 = kv4[s * 4 + 1];
        float4 f2 = kv4[s * 4 + 2];
        float l = qa.x * f0.x + qa.y * f0.y + qa.z * f0.z + qa.w * f0.w
                + qb.x * f1.x + qb.y * f1.y;
        float w = __expf(l);
        den += w;
        a0 += w * f1.z; a1 += w * f1.w;
        a2 += w * f2.x; a3 += w * f2.y;
        a4 += w * f2.z; a5 += w * f2.w;
    }

    float inv = 1.f / (den + 1e-16f);
    float4 s0 = *reinterpret_cast<const float4*>(g_qs + t * 16 + 8);
    float2 s1 = *reinterpret_cast<const float2*>(g_qs + t * 16 + 12);
    g_o2p[t * 2 + 0] = make_float4(a0 * inv + s0.x, a1 * inv + s0.y,
                                   a2 * inv + s0.z, a3 * inv + s0.w);
    g_o2p[t * 2 + 1] = make_float4(a4 * inv + s1.x, a5 * inv + s1.y, 0.f, 0.f);
}

// ---------------- pooling + output ----------------
__global__ void k_pool(const int* __restrict__ batch, int n) {
    __shared__ float ssum[GG * 6];
    __shared__ float scnt[GG];
    __shared__ int   sflag[GG];
    int tid = threadIdx.x;
    for (int i = tid; i < GG * 6; i += blockDim.x) ssum[i] = 0.f;
    for (int i = tid; i < GG; i += blockDim.x) { scnt[i] = 0.f; sflag[i] = 0; }
    __syncthreads();

    int node = blockIdx.x * blockDim.x + tid;
    if (node < n) {
        int g = __ldg(&batch[node]);
        float4 p0 = g_o2p[node * 2 + 0];
        float4 p1 = g_o2p[node * 2 + 1];
        atomicAdd(&ssum[g * 6 + 0], p0.x);
        atomicAdd(&ssum[g * 6 + 1], p0.y);
        atomicAdd(&ssum[g * 6 + 2], p0.z);
        atomicAdd(&ssum[g * 6 + 3], p0.w);
        atomicAdd(&ssum[g * 6 + 4], p1.x);
        atomicAdd(&ssum[g * 6 + 5], p1.y);
        atomicAdd(&scnt[g], 1.f);
        sflag[g] = 1;
    }
    __syncthreads();
    for (int g = tid; g < GG; g += blockDim.x) {
        if (sflag[g]) {
            atomicAdd(&g_cnt[g], scnt[g]);
#pragma unroll
            for (int c = 0; c < 6; c++)
                atomicAdd(&g_sums[g * 6 + c], ssum[g * 6 + c]);
        }
    }
}

__global__ void k_out(float* __restrict__ out) {
    int g = threadIdx.x;
    if (g >= GG) return;
    float cnt = fmaxf(g_cnt[g], 1.f);
    float p[6];
    float m = -INFINITY;
#pragma unroll
    for (int c = 0; c < 6; c++) { p[c] = g_sums[g * 6 + c] / cnt; m = fmaxf(m, p[c]); }
    float s = 0.f;
#pragma unroll
    for (int c = 0; c < 6; c++) s += expf(p[c] - m);
    float lse = m + logf(s);
#pragma unroll
    for (int c = 0; c < 6; c++) out[g * 6 + c] = p[c] - lse;
}

// ---------------- launch ----------------
extern "C" void kernel_launch(void* const* d_in, const int* in_sizes, int n_in,
                              void* d_out, int out_size) {
    const float* x    = (const float*)d_in[0];
    const int*   ei   = (const int*)  d_in[1];
    const int*   batch= (const int*)  d_in[2];
    const float* Wq1  = (const float*)d_in[3];
    const float* bq1  = (const float*)d_in[4];
    const float* Wk1  = (const float*)d_in[5];
    const float* bk1  = (const float*)d_in[6];
    const float* Wv1  = (const float*)d_in[7];
    const float* bv1  = (const float*)d_in[8];
    const float* Ws1  = (const float*)d_in[9];
    const float* bs1  = (const float*)d_in[10];
    const float* Wq2  = (const float*)d_in[11];
    const float* bq2  = (const float*)d_in[12];
    const float* Wk2  = (const float*)d_in[13];
    const float* bk2  = (const float*)d_in[14];
    const float* Wv2  = (const float*)d_in[15];
    const float* bv2  = (const float*)d_in[16];
    const float* Ws2  = (const float*)d_in[17];
    const float* bs2  = (const float*)d_in[18];
    float* out = (float*)d_out;

    int N = in_sizes[0] / 3;
    int E = in_sizes[1] / 2;
    const int* src = ei;
    const int* dst = ei + E;

    const int B = 256;
    int NB = (N + 1024) / 1024;   // covers i == N for rowptr[N]

    k_prep<<<(N * 4 + B - 1) / B, B>>>(x, Wq1, bq1, Wk1, bk1, N);
    k_hist<<<(E + B - 1) / B, B>>>(dst, E);
    k_scan_blk<<<NB, 1024>>>(N);
    k_scan_wr<<<NB, 1024>>>(N, E, NB);
    k_scatter<<<(E + B - 1) / B, B>>>(src, dst, E);
    k_attn1<<<(N + B - 1) / B, B>>>(N);
    k_gemm2<<<(N + 7) / 8, B>>>(Wv1, bv1, Ws1, bs1,
                                Wq2, bq2, Wk2, bk2, Wv2, bv2, Ws2, bs2, N);
    k_attn2<<<(N + B - 1) / B, B>>>(N);
    k_pool<<<(N + B - 1) / B, B>>>(batch, N);
    k_out<<<1, 64>>>(out);
}

// round 9
// speedup vs baseline: 6.3904x; 1.0817x over previous
#include <cuda_runtime.h>
#include <cuda_fp16.h>
#include <math.h>

#define NN 100000
#define EE 3200000
#define GG 64

// ---------------- static device scratch ----------------
__device__ float4 g_x4[NN];          // padded x
__device__ float4 g_cf[NN * 4];      // per (node,head): (e0,e1,e2,d0) pre-scaled
__device__ float4 g_ds[NN * 4];      // per (node,head): (den, sx0, sx1, sx2)

__device__ __half g_kvh[NN * 16];    // 32B/node: [0..5]=k2 half, [6..11]=v2 half, pad
__device__ float  g_qs[NN * 16];     // [0..5]=q2 (pre-scaled), [8..13]=s2
__device__ float4 g_o2p[NN * 2];     // padded layer-2 output (6 used)

__device__ int g_deg   [NN];
__device__ int g_rowptr[NN + 1];
__device__ int g_cursor[NN];
__device__ int g_csrsrc[EE];
__device__ int g_bsum[128];
__device__ int g_ticket;

__device__ float g_sums[GG * 6];
__device__ float g_cnt [GG];

// ---------------- fused prep: zero + x4 + coef ----------------
__global__ void k_prep(const float* __restrict__ x,
                       const float* __restrict__ Wq, const float* __restrict__ bq,
                       const float* __restrict__ Wk, const float* __restrict__ bk,
                       int n) {
    int idx = blockIdx.x * blockDim.x + threadIdx.x;
    if (idx < GG * 6) g_sums[idx] = 0.f;
    if (idx < GG) g_cnt[idx] = 0.f;
    if (idx == 0) g_ticket = 0;
    if (idx >= n * 4) return;
    int node = idx >> 2, h = idx & 3;
    float x0 = __ldg(&x[node * 3 + 0]);
    float x1 = __ldg(&x[node * 3 + 1]);
    float x2 = __ldg(&x[node * 3 + 2]);
    if (h == 0) {
        g_deg[node] = 0;
        g_x4[node] = make_float4(x0, x1, x2, 0.f);
    }
    float d0 = 0.f, e0 = 0.f, e1 = 0.f, e2 = 0.f;
    int base = h * 16;
#pragma unroll
    for (int c = 0; c < 16; c++) {
        int cc = base + c;
        float qc = bq[cc] + x0 * Wq[cc] + x1 * Wq[64 + cc] + x2 * Wq[128 + cc];
        d0 += qc * bk[cc];
        e0 += qc * Wk[cc];
        e1 += qc * Wk[64 + cc];
        e2 += qc * Wk[128 + cc];
    }
    g_cf[idx] = make_float4(e0 * 0.25f, e1 * 0.25f, e2 * 0.25f, d0 * 0.25f);
}

// ---------------- CSR build ----------------
__global__ void k_hist(const int* __restrict__ dst, int e) {
    int i = blockIdx.x * blockDim.x + threadIdx.x;
    if (i < e) atomicAdd(&g_deg[dst[i]], 1);
}

__global__ void k_scan_blk(int n) {
    __shared__ int wsum[32];
    int i = blockIdx.x * 1024 + threadIdx.x;
    int v = (i < n) ? g_deg[i] : 0;
#pragma unroll
    for (int off = 16; off > 0; off >>= 1)
        v += __shfl_xor_sync(0xFFFFFFFFu, v, off);
    int lane = threadIdx.x & 31, wid = threadIdx.x >> 5;
    if (lane == 0) wsum[wid] = v;
    __syncthreads();
    if (wid == 0) {
        int s = wsum[lane];
#pragma unroll
        for (int off = 16; off > 0; off >>= 1)
            s += __shfl_xor_sync(0xFFFFFFFFu, s, off);
        if (lane == 0) g_bsum[blockIdx.x] = s;
    }
}

__global__ void k_scan_wr(int n, int e, int nb) {
    __shared__ int wsum[32];
    __shared__ int sboff;
    int lane = threadIdx.x & 31, wid = threadIdx.x >> 5;

    if (wid == 0) {
        int acc = 0;
        for (int j = lane; j < nb; j += 32)
            acc += (j < blockIdx.x) ? g_bsum[j] : 0;
#pragma unroll
        for (int off = 16; off > 0; off >>= 1)
            acc += __shfl_xor_sync(0xFFFFFFFFu, acc, off);
        if (lane == 0) sboff = acc;
    }

    int i = blockIdx.x * 1024 + threadIdx.x;
    int v = (i < n) ? g_deg[i] : 0;
    int x = v;
#pragma unroll
    for (int off = 1; off < 32; off <<= 1) {
        int y = __shfl_up_sync(0xFFFFFFFFu, x, off);
        if (lane >= off) x += y;
    }
    if (lane == 31) wsum[wid] = x;
    __syncthreads();
    if (wid == 0) {
        int w = wsum[lane];
#pragma unroll
        for (int off = 1; off < 32; off <<= 1) {
            int y = __shfl_up_sync(0xFFFFFFFFu, w, off);
            if (lane >= off) w += y;
        }
        wsum[lane] = w;
    }
    __syncthreads();
    int excl = x - v + ((wid > 0) ? wsum[wid - 1] : 0) + sboff;
    if (i < n) { g_rowptr[i] = excl; g_cursor[i] = excl; }
    if (i == n) g_rowptr[n] = e;
}

__global__ void k_scatter(const int* __restrict__ src, const int* __restrict__ dst, int e) {
    int i = blockIdx.x * blockDim.x + threadIdx.x;
    if (i >= e) return;
    int p = atomicAdd(&g_cursor[dst[i]], 1);
    g_csrsrc[p] = src[i];
}

// ---------------- attention layer 1: 4 lanes per node ----------------
__global__ void k_attn1(int n) {
    int gt = blockIdx.x * blockDim.x + threadIdx.x;
    int node = gt >> 2;
    int sub = gt & 3;
    bool valid = (node < n);

    float4 cf0, cf1, cf2, cf3;
    int beg = 0, end = 0;
    if (valid) {
        cf0 = g_cf[node * 4 + 0];
        cf1 = g_cf[node * 4 + 1];
        cf2 = g_cf[node * 4 + 2];
        cf3 = g_cf[node * 4 + 3];
        beg = g_rowptr[node];
        end = g_rowptr[node + 1];
    }

    float4 ds0 = make_float4(0.f, 0.f, 0.f, 0.f);
    float4 ds1 = make_float4(0.f, 0.f, 0.f, 0.f);
    float4 ds2 = make_float4(0.f, 0.f, 0.f, 0.f);
    float4 ds3 = make_float4(0.f, 0.f, 0.f, 0.f);

    for (int i = beg + sub; i < end; i += 4) {
        int s = g_csrsrc[i];
        float4 xs = g_x4[s];
        float w0 = __expf(cf0.w + cf0.x * xs.x + cf0.y * xs.y + cf0.z * xs.z);
        float w1 = __expf(cf1.w + cf1.x * xs.x + cf1.y * xs.y + cf1.z * xs.z);
        float w2 = __expf(cf2.w + cf2.x * xs.x + cf2.y * xs.y + cf2.z * xs.z);
        float w3 = __expf(cf3.w + cf3.x * xs.x + cf3.y * xs.y + cf3.z * xs.z);
        ds0.x += w0; ds0.y += w0 * xs.x; ds0.z += w0 * xs.y; ds0.w += w0 * xs.z;
        ds1.x += w1; ds1.y += w1 * xs.x; ds1.z += w1 * xs.y; ds1.w += w1 * xs.z;
        ds2.x += w2; ds2.y += w2 * xs.x; ds2.z += w2 * xs.y; ds2.w += w2 * xs.z;
        ds3.x += w3; ds3.y += w3 * xs.x; ds3.z += w3 * xs.y; ds3.w += w3 * xs.z;
    }

    // merge over the quad (offsets 1, 2); all 32 lanes participate
#pragma unroll
    for (int off = 1; off <= 2; off <<= 1) {
        ds0.x += __shfl_xor_sync(0xFFFFFFFFu, ds0.x, off);
        ds0.y += __shfl_xor_sync(0xFFFFFFFFu, ds0.y, off);
        ds0.z += __shfl_xor_sync(0xFFFFFFFFu, ds0.z, off);
        ds0.w += __shfl_xor_sync(0xFFFFFFFFu, ds0.w, off);
        ds1.x += __shfl_xor_sync(0xFFFFFFFFu, ds1.x, off);
        ds1.y += __shfl_xor_sync(0xFFFFFFFFu, ds1.y, off);
        ds1.z += __shfl_xor_sync(0xFFFFFFFFu, ds1.z, off);
        ds1.w += __shfl_xor_sync(0xFFFFFFFFu, ds1.w, off);
        ds2.x += __shfl_xor_sync(0xFFFFFFFFu, ds2.x, off);
        ds2.y += __shfl_xor_sync(0xFFFFFFFFu, ds2.y, off);
        ds2.z += __shfl_xor_sync(0xFFFFFFFFu, ds2.z, off);
        ds2.w += __shfl_xor_sync(0xFFFFFFFFu, ds2.w, off);
        ds3.x += __shfl_xor_sync(0xFFFFFFFFu, ds3.x, off);
        ds3.y += __shfl_xor_sync(0xFFFFFFFFu, ds3.y, off);
        ds3.z += __shfl_xor_sync(0xFFFFFFFFu, ds3.z, off);
        ds3.w += __shfl_xor_sync(0xFFFFFFFFu, ds3.w, off);
    }

    if (valid) {
        // lane `sub` writes head record `sub` -> 64B coalesced per quad
        float4 myds = (sub == 0) ? ds0 : (sub == 1) ? ds1 : (sub == 2) ? ds2 : ds3;
        g_ds[node * 4 + sub] = myds;
    }
}

// ---------------- layer 2 projection (with fused layer-1 epilogue) ----------------
__global__ void k_gemm2(const float* __restrict__ Wv1, const float* __restrict__ bv1,
                        const float* __restrict__ Ws1, const float* __restrict__ bs1,
                        const float* __restrict__ Wq, const float* __restrict__ bq,
                        const float* __restrict__ Wk, const float* __restrict__ bk,
                        const float* __restrict__ Wv, const float* __restrict__ bv,
                        const float* __restrict__ Ws, const float* __restrict__ bs,
                        int n) {
    __shared__ float  shH[8][64];
    __shared__ float  shW2[4][390];
    __shared__ float  shB2[4][6];
    __shared__ float  shWv[192], shBv[64], shWs[192], shBs[64];
    __shared__ float4 shDS[32];
    __shared__ float4 shX[8];
    int tid = threadIdx.x;
    int blk = blockIdx.x;

    for (int i = tid; i < 384 * 4; i += 256) {
        int mm = i / 384, r = i % 384;
        const float* W = (mm == 0) ? Wq : (mm == 1) ? Wk : (mm == 2) ? Wv : Ws;
        shW2[mm][r] = W[r];
    }
    if (tid < 24) {
        int mm = tid / 6, cc = tid % 6;
        const float* b = (mm == 0) ? bq : (mm == 1) ? bk : (mm == 2) ? bv : bs;
        shB2[mm][cc] = b[cc];
    }
    if (tid < 192) { shWv[tid] = Wv1[tid]; shWs[tid] = Ws1[tid]; }
    else if (tid < 256) { shBv[tid - 192] = bv1[tid - 192]; shBs[tid - 192] = bs1[tid - 192]; }
    if (tid < 32) {
        int gidx = blk * 32 + tid;
        shDS[tid] = (gidx < n * 4) ? g_ds[gidx] : make_float4(0.f, 0.f, 0.f, 0.f);
    }
    if (tid < 8) {
        int node = blk * 8 + tid;
        shX[tid] = (node < n) ? g_x4[node] : make_float4(0.f, 0.f, 0.f, 0.f);
    }
    __syncthreads();

#pragma unroll
    for (int r = 0; r < 2; r++) {
        int idx = tid + r * 256;
        int local = idx >> 6, c = idx & 63;
        float4 ds = shDS[local * 4 + (c >> 4)];
        float4 xt = shX[local];
        float num = shBv[c] * ds.x + shWv[c] * ds.y + shWv[64 + c] * ds.z + shWv[128 + c] * ds.w;
        float val = num / (ds.x + 1e-16f)
                  + shBs[c] + xt.x * shWs[c] + xt.y * shWs[64 + c] + xt.z * shWs[128 + c];
        shH[local][c] = fmaxf(val, 0.f);
    }
    __syncthreads();

    int w = tid >> 5;
    int lane = tid & 31;
    int node = blk * 8 + w;
    if (node >= n || lane >= 24) return;
    int mm = lane / 6, cc = lane % 6;
    float acc = shB2[mm][cc];
#pragma unroll
    for (int k = 0; k < 64; k++) acc += shH[w][k] * shW2[mm][k * 6 + cc];
    if (mm == 0)      g_qs[node * 16 + cc]     = acc * 0.4082482904638631f;
    else if (mm == 1) g_kvh[node * 16 + cc]     = __float2half(acc);   // k
    else if (mm == 2) g_kvh[node * 16 + 6 + cc] = __float2half(acc);   // v
    else              g_qs[node * 16 + 8 + cc] = acc;
}

// ---------------- attention layer 2: 4 lanes per node, half kv ----------------
__global__ void k_attn2(int n) {
    int gt = blockIdx.x * blockDim.x + threadIdx.x;
    int node = gt >> 2;
    int sub = gt & 3;
    bool valid = (node < n);

    float4 qa = make_float4(0.f, 0.f, 0.f, 0.f);
    float2 qb = make_float2(0.f, 0.f);
    int beg = 0, end = 0;
    if (valid) {
        qa = *reinterpret_cast<const float4*>(g_qs + node * 16);
        qb = *reinterpret_cast<const float2*>(g_qs + node * 16 + 4);
        beg = g_rowptr[node];
        end = g_rowptr[node + 1];
    }

    const uint4* kv = reinterpret_cast<const uint4*>(g_kvh);

    float den = 0.f;
    float a0 = 0.f, a1 = 0.f, a2 = 0.f, a3 = 0.f, a4 = 0.f, a5 = 0.f;

    for (int i = beg + sub; i < end; i += 4) {
        int s = g_csrsrc[i];
        uint4 r0 = kv[s * 2 + 0];    // k0..k5, v0, v1 (halves)
        uint4 r1 = kv[s * 2 + 1];    // v2..v5, pad
        float2 k01 = __half22float2(*reinterpret_cast<const __half2*>(&r0.x));
        float2 k23 = __half22float2(*reinterpret_cast<const __half2*>(&r0.y));
        float2 k45 = __half22float2(*reinterpret_cast<const __half2*>(&r0.z));
        float2 v01 = __half22float2(*reinterpret_cast<const __half2*>(&r0.w));
        float2 v23 = __half22float2(*reinterpret_cast<const __half2*>(&r1.x));
        float2 v45 = __half22float2(*reinterpret_cast<const __half2*>(&r1.y));
        float l = qa.x * k01.x + qa.y * k01.y + qa.z * k23.x + qa.w * k23.y
                + qb.x * k45.x + qb.y * k45.y;
        float w = __expf(l);
        den += w;
        a0 += w * v01.x; a1 += w * v01.y;
        a2 += w * v23.x; a3 += w * v23.y;
        a4 += w * v45.x; a5 += w * v45.y;
    }

#pragma unroll
    for (int off = 1; off <= 2; off <<= 1) {
        den += __shfl_xor_sync(0xFFFFFFFFu, den, off);
        a0 += __shfl_xor_sync(0xFFFFFFFFu, a0, off);
        a1 += __shfl_xor_sync(0xFFFFFFFFu, a1, off);
        a2 += __shfl_xor_sync(0xFFFFFFFFu, a2, off);
        a3 += __shfl_xor_sync(0xFFFFFFFFu, a3, off);
        a4 += __shfl_xor_sync(0xFFFFFFFFu, a4, off);
        a5 += __shfl_xor_sync(0xFFFFFFFFu, a5, off);
    }

    if (valid && sub < 2) {
        float inv = 1.f / (den + 1e-16f);
        if (sub == 0) {
            float4 s0 = *reinterpret_cast<const float4*>(g_qs + node * 16 + 8);
            g_o2p[node * 2 + 0] = make_float4(a0 * inv + s0.x, a1 * inv + s0.y,
                                              a2 * inv + s0.z, a3 * inv + s0.w);
        } else {
            float2 s1 = *reinterpret_cast<const float2*>(g_qs + node * 16 + 12);
            g_o2p[node * 2 + 1] = make_float4(a4 * inv + s1.x, a5 * inv + s1.y, 0.f, 0.f);
        }
    }
}

// ---------------- pooling + output (fused via ticket) ----------------
__global__ void k_pool(const int* __restrict__ batch, int n, float* __restrict__ out) {
    __shared__ float ssum[GG * 6];
    __shared__ float scnt[GG];
    __shared__ int   sflag[GG];
    __shared__ int   slast;
    int tid = threadIdx.x;
    for (int i = tid; i < GG * 6; i += blockDim.x) ssum[i] = 0.f;
    for (int i = tid; i < GG; i += blockDim.x) { scnt[i] = 0.f; sflag[i] = 0; }
    __syncthreads();

    int node = blockIdx.x * blockDim.x + tid;
    if (node < n) {
        int g = __ldg(&batch[node]);
        float4 p0 = g_o2p[node * 2 + 0];
        float4 p1 = g_o2p[node * 2 + 1];
        atomicAdd(&ssum[g * 6 + 0], p0.x);
        atomicAdd(&ssum[g * 6 + 1], p0.y);
        atomicAdd(&ssum[g * 6 + 2], p0.z);
        atomicAdd(&ssum[g * 6 + 3], p0.w);
        atomicAdd(&ssum[g * 6 + 4], p1.x);
        atomicAdd(&ssum[g * 6 + 5], p1.y);
        atomicAdd(&scnt[g], 1.f);
        sflag[g] = 1;
    }
    __syncthreads();
    for (int g = tid; g < GG; g += blockDim.x) {
        if (sflag[g]) {
            atomicAdd(&g_cnt[g], scnt[g]);
#pragma unroll
            for (int c = 0; c < 6; c++)
                atomicAdd(&g_sums[g * 6 + c], ssum[g * 6 + c]);
        }
    }
    __syncthreads();
    if (tid == 0) {
        __threadfence();
        int t = atomicAdd(&g_ticket, 1);
        slast = (t == (int)gridDim.x - 1) ? 1 : 0;
    }
    __syncthreads();
    if (slast) {
        __threadfence();
        int g = tid;
        if (g < GG) {
            float cnt = fmaxf(g_cnt[g], 1.f);
            float p[6];
            float m = -INFINITY;
#pragma unroll
            for (int c = 0; c < 6; c++) { p[c] = g_sums[g * 6 + c] / cnt; m = fmaxf(m, p[c]); }
            float s = 0.f;
#pragma unroll
            for (int c = 0; c < 6; c++) s += expf(p[c] - m);
            float lse = m + logf(s);
#pragma unroll
            for (int c = 0; c < 6; c++) out[g * 6 + c] = p[c] - lse;
        }
    }
}

// ---------------- launch ----------------
extern "C" void kernel_launch(void* const* d_in, const int* in_sizes, int n_in,
                              void* d_out, int out_size) {
    const float* x    = (const float*)d_in[0];
    const int*   ei   = (const int*)  d_in[1];
    const int*   batch= (const int*)  d_in[2];
    const float* Wq1  = (const float*)d_in[3];
    const float* bq1  = (const float*)d_in[4];
    const float* Wk1  = (const float*)d_in[5];
    const float* bk1  = (const float*)d_in[6];
    const float* Wv1  = (const float*)d_in[7];
    const float* bv1  = (const float*)d_in[8];
    const float* Ws1  = (const float*)d_in[9];
    const float* bs1  = (const float*)d_in[10];
    const float* Wq2  = (const float*)d_in[11];
    const float* bq2  = (const float*)d_in[12];
    const float* Wk2  = (const float*)d_in[13];
    const float* bk2  = (const float*)d_in[14];
    const float* Wv2  = (const float*)d_in[15];
    const float* bv2  = (const float*)d_in[16];
    const float* Ws2  = (const float*)d_in[17];
    const float* bs2  = (const float*)d_in[18];
    float* out = (float*)d_out;

    int N = in_sizes[0] / 3;
    int E = in_sizes[1] / 2;
    const int* src = ei;
    const int* dst = ei + E;

    const int B = 256;
    int NB = (N + 1024) / 1024;

    k_prep<<<(N * 4 + B - 1) / B, B>>>(x, Wq1, bq1, Wk1, bk1, N);
    k_hist<<<(E + B - 1) / B, B>>>(dst, E);
    k_scan_blk<<<NB, 1024>>>(N);
    k_scan_wr<<<NB, 1024>>>(N, E, NB);
    k_scatter<<<(E + B - 1) / B, B>>>(src, dst, E);
    k_attn1<<<(N * 4 + B - 1) / B, B>>>(N);
    k_gemm2<<<(N + 7) / 8, B>>>(Wv1, bv1, Ws1, bs1,
                                Wq2, bq2, Wk2, bk2, Wv2, bv2, Ws2, bs2, N);
    k_attn2<<<(N * 4 + B - 1) / B, B>>>(N);
    k_pool<<<(N + B - 1) / B, B>>>(batch, N, out);
}

// round 10
// speedup vs baseline: 6.8424x; 1.0707x over previous
#include <cuda_runtime.h>
#include <cuda_fp16.h>
#include <math.h>

#define NN 100000
#define EE 3200000
#define GG 64

// ---------------- static device scratch (zero-initialized at module load) ----------------
__device__ float4 g_x4[NN];          // padded x
__device__ float4 g_cf[NN * 4];      // per (node,head): (e0,e1,e2,d0) pre-scaled
__device__ float4 g_ds[NN * 4];      // per (node,head): (den, sx0, sx1, sx2)

__device__ __half g_kvh[NN * 16];    // 32B/node: [0..5]=k2 half, [6..11]=v2 half, pad
__device__ float  g_qs[NN * 16];     // [0..5]=q2 (pre-scaled), [8..13]=s2
__device__ float4 g_o2p[NN * 2];     // padded layer-2 output (6 used)

__device__ int g_deg   [NN];         // invariant: zero on kernel_launch entry
__device__ int g_rowptr[NN + 1];
__device__ int g_rank  [EE];         // edge's arrival rank within its dst bucket
__device__ int g_csrsrc[EE];
__device__ int g_bsum[128];
__device__ int g_ticket;             // invariant: zero on entry

__device__ float g_sums[GG * 6];     // invariant: zero on entry
__device__ float g_cnt [GG];         // invariant: zero on entry

// ---------------- fused prep + hist ----------------
// idx < e:   histogram dst + record rank (atomicAdd return value)
// idx < n*4: per-(node,head) bilinear coefficients + padded x
__global__ void k_prep_hist(const float* __restrict__ x,
                            const int* __restrict__ dst,
                            const float* __restrict__ Wq, const float* __restrict__ bq,
                            const float* __restrict__ Wk, const float* __restrict__ bk,
                            int n, int e) {
    int idx = blockIdx.x * blockDim.x + threadIdx.x;
    if (idx < e)
        g_rank[idx] = atomicAdd(&g_deg[dst[idx]], 1);
    if (idx >= n * 4) return;
    int node = idx >> 2, h = idx & 3;
    float x0 = __ldg(&x[node * 3 + 0]);
    float x1 = __ldg(&x[node * 3 + 1]);
    float x2 = __ldg(&x[node * 3 + 2]);
    if (h == 0)
        g_x4[node] = make_float4(x0, x1, x2, 0.f);
    float d0 = 0.f, e0 = 0.f, e1 = 0.f, e2 = 0.f;
    int base = h * 16;
#pragma unroll
    for (int c = 0; c < 16; c++) {
        int cc = base + c;
        float qc = bq[cc] + x0 * Wq[cc] + x1 * Wq[64 + cc] + x2 * Wq[128 + cc];
        d0 += qc * bk[cc];
        e0 += qc * Wk[cc];
        e1 += qc * Wk[64 + cc];
        e2 += qc * Wk[128 + cc];
    }
    g_cf[idx] = make_float4(e0 * 0.25f, e1 * 0.25f, e2 * 0.25f, d0 * 0.25f);
}

// ---------------- scan ----------------
__global__ void k_scan_blk(int n) {
    __shared__ int wsum[32];
    int i = blockIdx.x * 1024 + threadIdx.x;
    int v = (i < n) ? g_deg[i] : 0;
#pragma unroll
    for (int off = 16; off > 0; off >>= 1)
        v += __shfl_xor_sync(0xFFFFFFFFu, v, off);
    int lane = threadIdx.x & 31, wid = threadIdx.x >> 5;
    if (lane == 0) wsum[wid] = v;
    __syncthreads();
    if (wid == 0) {
        int s = wsum[lane];
#pragma unroll
        for (int off = 16; off > 0; off >>= 1)
            s += __shfl_xor_sync(0xFFFFFFFFu, s, off);
        if (lane == 0) g_bsum[blockIdx.x] = s;
    }
}

// writes rowptr AND restores the g_deg==0 invariant for the next launch
__global__ void k_scan_wr(int n, int e, int nb) {
    __shared__ int wsum[32];
    __shared__ int sboff;
    int lane = threadIdx.x & 31, wid = threadIdx.x >> 5;

    if (wid == 0) {
        int acc = 0;
        for (int j = lane; j < nb; j += 32)
            acc += (j < blockIdx.x) ? g_bsum[j] : 0;
#pragma unroll
        for (int off = 16; off > 0; off >>= 1)
            acc += __shfl_xor_sync(0xFFFFFFFFu, acc, off);
        if (lane == 0) sboff = acc;
    }

    int i = blockIdx.x * 1024 + threadIdx.x;
    int v = (i < n) ? g_deg[i] : 0;
    int x = v;
#pragma unroll
    for (int off = 1; off < 32; off <<= 1) {
        int y = __shfl_up_sync(0xFFFFFFFFu, x, off);
        if (lane >= off) x += y;
    }
    if (lane == 31) wsum[wid] = x;
    __syncthreads();
    if (wid == 0) {
        int w = wsum[lane];
#pragma unroll
        for (int off = 1; off < 32; off <<= 1) {
            int y = __shfl_up_sync(0xFFFFFFFFu, w, off);
            if (lane >= off) w += y;
        }
        wsum[lane] = w;
    }
    __syncthreads();
    int excl = x - v + ((wid > 0) ? wsum[wid - 1] : 0) + sboff;
    if (i < n) { g_rowptr[i] = excl; g_deg[i] = 0; }
    if (i == n) g_rowptr[n] = e;
}

// ---------------- scatter (no atomics: rank-based placement) ----------------
__global__ void k_scatter(const int* __restrict__ src, const int* __restrict__ dst, int e) {
    int i = blockIdx.x * blockDim.x + threadIdx.x;
    if (i >= e) return;
    int p = g_rowptr[dst[i]] + g_rank[i];
    g_csrsrc[p] = src[i];
}

// ---------------- attention layer 1: 4 lanes per node ----------------
__global__ void k_attn1(int n) {
    int gt = blockIdx.x * blockDim.x + threadIdx.x;
    int node = gt >> 2;
    int sub = gt & 3;
    bool valid = (node < n);

    float4 cf0, cf1, cf2, cf3;
    int beg = 0, end = 0;
    if (valid) {
        cf0 = g_cf[node * 4 + 0];
        cf1 = g_cf[node * 4 + 1];
        cf2 = g_cf[node * 4 + 2];
        cf3 = g_cf[node * 4 + 3];
        beg = g_rowptr[node];
        end = g_rowptr[node + 1];
    }

    float4 ds0 = make_float4(0.f, 0.f, 0.f, 0.f);
    float4 ds1 = make_float4(0.f, 0.f, 0.f, 0.f);
    float4 ds2 = make_float4(0.f, 0.f, 0.f, 0.f);
    float4 ds3 = make_float4(0.f, 0.f, 0.f, 0.f);

    for (int i = beg + sub; i < end; i += 4) {
        int s = g_csrsrc[i];
        float4 xs = g_x4[s];
        float w0 = __expf(cf0.w + cf0.x * xs.x + cf0.y * xs.y + cf0.z * xs.z);
        float w1 = __expf(cf1.w + cf1.x * xs.x + cf1.y * xs.y + cf1.z * xs.z);
        float w2 = __expf(cf2.w + cf2.x * xs.x + cf2.y * xs.y + cf2.z * xs.z);
        float w3 = __expf(cf3.w + cf3.x * xs.x + cf3.y * xs.y + cf3.z * xs.z);
        ds0.x += w0; ds0.y += w0 * xs.x; ds0.z += w0 * xs.y; ds0.w += w0 * xs.z;
        ds1.x += w1; ds1.y += w1 * xs.x; ds1.z += w1 * xs.y; ds1.w += w1 * xs.z;
        ds2.x += w2; ds2.y += w2 * xs.x; ds2.z += w2 * xs.y; ds2.w += w2 * xs.z;
        ds3.x += w3; ds3.y += w3 * xs.x; ds3.z += w3 * xs.y; ds3.w += w3 * xs.z;
    }

#pragma unroll
    for (int off = 1; off <= 2; off <<= 1) {
        ds0.x += __shfl_xor_sync(0xFFFFFFFFu, ds0.x, off);
        ds0.y += __shfl_xor_sync(0xFFFFFFFFu, ds0.y, off);
        ds0.z += __shfl_xor_sync(0xFFFFFFFFu, ds0.z, off);
        ds0.w += __shfl_xor_sync(0xFFFFFFFFu, ds0.w, off);
        ds1.x += __shfl_xor_sync(0xFFFFFFFFu, ds1.x, off);
        ds1.y += __shfl_xor_sync(0xFFFFFFFFu, ds1.y, off);
        ds1.z += __shfl_xor_sync(0xFFFFFFFFu, ds1.z, off);
        ds1.w += __shfl_xor_sync(0xFFFFFFFFu, ds1.w, off);
        ds2.x += __shfl_xor_sync(0xFFFFFFFFu, ds2.x, off);
        ds2.y += __shfl_xor_sync(0xFFFFFFFFu, ds2.y, off);
        ds2.z += __shfl_xor_sync(0xFFFFFFFFu, ds2.z, off);
        ds2.w += __shfl_xor_sync(0xFFFFFFFFu, ds2.w, off);
        ds3.x += __shfl_xor_sync(0xFFFFFFFFu, ds3.x, off);
        ds3.y += __shfl_xor_sync(0xFFFFFFFFu, ds3.y, off);
        ds3.z += __shfl_xor_sync(0xFFFFFFFFu, ds3.z, off);
        ds3.w += __shfl_xor_sync(0xFFFFFFFFu, ds3.w, off);
    }

    if (valid) {
        float4 myds = (sub == 0) ? ds0 : (sub == 1) ? ds1 : (sub == 2) ? ds2 : ds3;
        g_ds[node * 4 + sub] = myds;
    }
}

// ---------------- layer 2 projection: 32 nodes/block, fused layer-1 epilogue ----------------
__global__ void __launch_bounds__(1024)
k_gemm2(const float* __restrict__ Wv1, const float* __restrict__ bv1,
        const float* __restrict__ Ws1, const float* __restrict__ bs1,
        const float* __restrict__ Wq, const float* __restrict__ bq,
        const float* __restrict__ Wk, const float* __restrict__ bk,
        const float* __restrict__ Wv, const float* __restrict__ bv,
        const float* __restrict__ Ws, const float* __restrict__ bs,
        int n) {
    __shared__ float  shH[32][64];     // 8KB
    __shared__ float  shW2[4][390];    // 6.24KB
    __shared__ float  shB2[4][6];
    __shared__ float  shWv[192], shBv[64], shWs[192], shBs[64];
    __shared__ float4 shDS[128];       // 32 nodes x 4 heads
    __shared__ float4 shX[32];
    int tid = threadIdx.x;
    int blk = blockIdx.x;

    for (int i = tid; i < 384 * 4; i += 1024) {
        int mm = i / 384, r = i % 384;
        const float* W = (mm == 0) ? Wq : (mm == 1) ? Wk : (mm == 2) ? Wv : Ws;
        shW2[mm][r] = W[r];
    }
    if (tid < 24) {
        int mm = tid / 6, cc = tid % 6;
        const float* b = (mm == 0) ? bq : (mm == 1) ? bk : (mm == 2) ? bv : bs;
        shB2[mm][cc] = b[cc];
    }
    if (tid < 192) { shWv[tid] = Wv1[tid]; shWs[tid] = Ws1[tid]; }
    else if (tid < 256) { shBv[tid - 192] = bv1[tid - 192]; shBs[tid - 192] = bs1[tid - 192]; }
    if (tid < 128) {
        int gidx = blk * 128 + tid;
        shDS[tid] = (gidx < n * 4) ? g_ds[gidx] : make_float4(0.f, 0.f, 0.f, 0.f);
    }
    if (tid < 32) {
        int node = blk * 32 + tid;
        shX[tid] = (node < n) ? g_x4[node] : make_float4(0.f, 0.f, 0.f, 0.f);
    }
    __syncthreads();

    // reconstruct h: 32*64 = 2048 values, 2 per thread
#pragma unroll
    for (int r = 0; r < 2; r++) {
        int idx = tid + r * 1024;
        int local = idx >> 6, c = idx & 63;
        float4 ds = shDS[local * 4 + (c >> 4)];
        float4 xt = shX[local];
        float num = shBv[c] * ds.x + shWv[c] * ds.y + shWv[64 + c] * ds.z + shWv[128 + c] * ds.w;
        float val = num / (ds.x + 1e-16f)
                  + shBs[c] + xt.x * shWs[c] + xt.y * shWs[64 + c] + xt.z * shWs[128 + c];
        shH[local][c] = fmaxf(val, 0.f);
    }
    __syncthreads();

    int w = tid >> 5;                 // warp = local node (0..31)
    int lane = tid & 31;
    int node = blk * 32 + w;
    if (node >= n || lane >= 24) return;
    int mm = lane / 6, cc = lane % 6;
    float acc = shB2[mm][cc];
#pragma unroll
    for (int k = 0; k < 64; k++) acc += shH[w][k] * shW2[mm][k * 6 + cc];
    if (mm == 0)      g_qs[node * 16 + cc]      = acc * 0.4082482904638631f;
    else if (mm == 1) g_kvh[node * 16 + cc]     = __float2half(acc);
    else if (mm == 2) g_kvh[node * 16 + 6 + cc] = __float2half(acc);
    else              g_qs[node * 16 + 8 + cc]  = acc;
}

// ---------------- attention layer 2: 4 lanes per node, half kv ----------------
__global__ void k_attn2(int n) {
    int gt = blockIdx.x * blockDim.x + threadIdx.x;
    int node = gt >> 2;
    int sub = gt & 3;
    bool valid = (node < n);

    float4 qa = make_float4(0.f, 0.f, 0.f, 0.f);
    float2 qb = make_float2(0.f, 0.f);
    int beg = 0, end = 0;
    if (valid) {
        qa = *reinterpret_cast<const float4*>(g_qs + node * 16);
        qb = *reinterpret_cast<const float2*>(g_qs + node * 16 + 4);
        beg = g_rowptr[node];
        end = g_rowptr[node + 1];
    }

    const uint4* kv = reinterpret_cast<const uint4*>(g_kvh);

    float den = 0.f;
    float a0 = 0.f, a1 = 0.f, a2 = 0.f, a3 = 0.f, a4 = 0.f, a5 = 0.f;

    for (int i = beg + sub; i < end; i += 4) {
        int s = g_csrsrc[i];
        uint4 r0 = kv[s * 2 + 0];
        uint4 r1 = kv[s * 2 + 1];
        float2 k01 = __half22float2(*reinterpret_cast<const __half2*>(&r0.x));
        float2 k23 = __half22float2(*reinterpret_cast<const __half2*>(&r0.y));
        float2 k45 = __half22float2(*reinterpret_cast<const __half2*>(&r0.z));
        float2 v01 = __half22float2(*reinterpret_cast<const __half2*>(&r0.w));
        float2 v23 = __half22float2(*reinterpret_cast<const __half2*>(&r1.x));
        float2 v45 = __half22float2(*reinterpret_cast<const __half2*>(&r1.y));
        float l = qa.x * k01.x + qa.y * k01.y + qa.z * k23.x + qa.w * k23.y
                + qb.x * k45.x + qb.y * k45.y;
        float w = __expf(l);
        den += w;
        a0 += w * v01.x; a1 += w * v01.y;
        a2 += w * v23.x; a3 += w * v23.y;
        a4 += w * v45.x; a5 += w * v45.y;
    }

#pragma unroll
    for (int off = 1; off <= 2; off <<= 1) {
        den += __shfl_xor_sync(0xFFFFFFFFu, den, off);
        a0 += __shfl_xor_sync(0xFFFFFFFFu, a0, off);
        a1 += __shfl_xor_sync(0xFFFFFFFFu, a1, off);
        a2 += __shfl_xor_sync(0xFFFFFFFFu, a2, off);
        a3 += __shfl_xor_sync(0xFFFFFFFFu, a3, off);
        a4 += __shfl_xor_sync(0xFFFFFFFFu, a4, off);
        a5 += __shfl_xor_sync(0xFFFFFFFFu, a5, off);
    }

    if (valid && sub < 2) {
        float inv = 1.f / (den + 1e-16f);
        if (sub == 0) {
            float4 s0 = *reinterpret_cast<const float4*>(g_qs + node * 16 + 8);
            g_o2p[node * 2 + 0] = make_float4(a0 * inv + s0.x, a1 * inv + s0.y,
                                              a2 * inv + s0.z, a3 * inv + s0.w);
        } else {
            float2 s1 = *reinterpret_cast<const float2*>(g_qs + node * 16 + 12);
            g_o2p[node * 2 + 1] = make_float4(a4 * inv + s1.x, a5 * inv + s1.y, 0.f, 0.f);
        }
    }
}

// ---------------- pooling + output + state cleanup (ticket) ----------------
__global__ void k_pool(const int* __restrict__ batch, int n, float* __restrict__ out) {
    __shared__ float ssum[GG * 6];
    __shared__ float scnt[GG];
    __shared__ int   sflag[GG];
    __shared__ int   slast;
    int tid = threadIdx.x;
    for (int i = tid; i < GG * 6; i += blockDim.x) ssum[i] = 0.f;
    for (int i = tid; i < GG; i += blockDim.x) { scnt[i] = 0.f; sflag[i] = 0; }
    __syncthreads();

    int node = blockIdx.x * blockDim.x + tid;
    if (node < n) {
        int g = __ldg(&batch[node]);
        float4 p0 = g_o2p[node * 2 + 0];
        float4 p1 = g_o2p[node * 2 + 1];
        atomicAdd(&ssum[g * 6 + 0], p0.x);
        atomicAdd(&ssum[g * 6 + 1], p0.y);
        atomicAdd(&ssum[g * 6 + 2], p0.z);
        atomicAdd(&ssum[g * 6 + 3], p0.w);
        atomicAdd(&ssum[g * 6 + 4], p1.x);
        atomicAdd(&ssum[g * 6 + 5], p1.y);
        atomicAdd(&scnt[g], 1.f);
        sflag[g] = 1;
    }
    __syncthreads();
    for (int g = tid; g < GG; g += blockDim.x) {
        if (sflag[g]) {
            atomicAdd(&g_cnt[g], scnt[g]);
#pragma unroll
            for (int c = 0; c < 6; c++)
                atomicAdd(&g_sums[g * 6 + c], ssum[g * 6 + c]);
        }
    }
    __syncthreads();
    if (tid == 0) {
        __threadfence();
        int t = atomicAdd(&g_ticket, 1);
        slast = (t == (int)gridDim.x - 1) ? 1 : 0;
    }
    __syncthreads();
    if (slast) {
        __threadfence();
        int g = tid;
        if (g < GG) {
            float cnt = fmaxf(g_cnt[g], 1.f);
            float p[6];
            float m = -INFINITY;
#pragma unroll
            for (int c = 0; c < 6; c++) { p[c] = g_sums[g * 6 + c] / cnt; m = fmaxf(m, p[c]); }
            float s = 0.f;
#pragma unroll
            for (int c = 0; c < 6; c++) s += expf(p[c] - m);
            float lse = m + logf(s);
#pragma unroll
            for (int c = 0; c < 6; c++) out[g * 6 + c] = p[c] - lse;
        }
        __syncthreads();
        // restore the zero-state invariant for the next launch
        for (int i = tid; i < GG * 6; i += blockDim.x) g_sums[i] = 0.f;
        for (int i = tid; i < GG; i += blockDim.x) g_cnt[i] = 0.f;
        if (tid == 0) g_ticket = 0;
    }
}

// ---------------- launch ----------------
extern "C" void kernel_launch(void* const* d_in, const int* in_sizes, int n_in,
                              void* d_out, int out_size) {
    const float* x    = (const float*)d_in[0];
    const int*   ei   = (const int*)  d_in[1];
    const int*   batch= (const int*)  d_in[2];
    const float* Wq1  = (const float*)d_in[3];
    const float* bq1  = (const float*)d_in[4];
    const float* Wk1  = (const float*)d_in[5];
    const float* bk1  = (const float*)d_in[6];
    const float* Wv1  = (const float*)d_in[7];
    const float* bv1  = (const float*)d_in[8];
    const float* Ws1  = (const float*)d_in[9];
    const float* bs1  = (const float*)d_in[10];
    const float* Wq2  = (const float*)d_in[11];
    const float* bq2  = (const float*)d_in[12];
    const float* Wk2  = (const float*)d_in[13];
    const float* bk2  = (const float*)d_in[14];
    const float* Wv2  = (const float*)d_in[15];
    const float* bv2  = (const float*)d_in[16];
    const float* Ws2  = (const float*)d_in[17];
    const float* bs2  = (const float*)d_in[18];
    float* out = (float*)d_out;

    int N = in_sizes[0] / 3;
    int E = in_sizes[1] / 2;
    const int* src = ei;
    const int* dst = ei + E;

    const int B = 256;
    int NB = (N + 1024) / 1024;   // covers i == N for rowptr[N]

    k_prep_hist<<<(E + B - 1) / B, B>>>(x, dst, Wq1, bq1, Wk1, bk1, N, E);
    k_scan_blk<<<NB, 1024>>>(N);
    k_scan_wr<<<NB, 1024>>>(N, E, NB);
    k_scatter<<<(E + B - 1) / B, B>>>(src, dst, E);
    k_attn1<<<(N * 4 + B - 1) / B, B>>>(N);
    k_gemm2<<<(N + 31) / 32, 1024>>>(Wv1, bv1, Ws1, bs1,
                                     Wq2, bq2, Wk2, bk2, Wv2, bv2, Ws2, bs2, N);
    k_attn2<<<(N * 4 + B - 1) / B, B>>>(N);
    k_pool<<<(N + B - 1) / B, B>>>(batch, N, out);
}

// round 11
// speedup vs baseline: 7.4868x; 1.0942x over previous
#include <cuda_runtime.h>
#include <cuda_fp16.h>
#include <math.h>

#define NN 100000
#define EE 3200000
#define GG 64

// ---------------- static device scratch (zero-initialized at module load) ----------------
__device__ float4 g_x4[NN];          // padded x
__device__ float4 g_cf[NN * 4];      // per (node,head): (e0,e1,e2,d0) pre-scaled
__device__ float4 g_ds[NN * 4];      // per (node,head): (den, sx0, sx1, sx2)

__device__ __half g_kvh[NN * 16];    // 32B/node: [0..5]=k2 half, [6..11]=v2 half, pad
__device__ float  g_qs[NN * 16];     // [0..5]=q2 (pre-scaled), [8..13]=s2

__device__ int g_deg   [NN];         // invariant: zero on kernel_launch entry
__device__ int g_rowptr[NN + 1];
__device__ int g_rank  [EE];
__device__ int g_csrsrc[EE];
__device__ int g_bsum[128];
__device__ int g_ticket;             // invariant: zero on entry

__device__ float g_sums[GG * 6];     // invariant: zero on entry
__device__ float g_cnt [GG];         // invariant: zero on entry

// ---------------- fused prep + hist ----------------
__global__ void k_prep_hist(const float* __restrict__ x,
                            const int* __restrict__ dst,
                            const float* __restrict__ Wq, const float* __restrict__ bq,
                            const float* __restrict__ Wk, const float* __restrict__ bk,
                            int n, int e) {
    int idx = blockIdx.x * blockDim.x + threadIdx.x;
    if (idx < e)
        g_rank[idx] = atomicAdd(&g_deg[dst[idx]], 1);
    if (idx >= n * 4) return;
    int node = idx >> 2, h = idx & 3;
    float x0 = __ldg(&x[node * 3 + 0]);
    float x1 = __ldg(&x[node * 3 + 1]);
    float x2 = __ldg(&x[node * 3 + 2]);
    if (h == 0)
        g_x4[node] = make_float4(x0, x1, x2, 0.f);
    float d0 = 0.f, e0 = 0.f, e1 = 0.f, e2 = 0.f;
    int base = h * 16;
#pragma unroll
    for (int c = 0; c < 16; c++) {
        int cc = base + c;
        float qc = bq[cc] + x0 * Wq[cc] + x1 * Wq[64 + cc] + x2 * Wq[128 + cc];
        d0 += qc * bk[cc];
        e0 += qc * Wk[cc];
        e1 += qc * Wk[64 + cc];
        e2 += qc * Wk[128 + cc];
    }
    g_cf[idx] = make_float4(e0 * 0.25f, e1 * 0.25f, e2 * 0.25f, d0 * 0.25f);
}

// ---------------- scan ----------------
__global__ void k_scan_blk(int n) {
    __shared__ int wsum[32];
    int i = blockIdx.x * 1024 + threadIdx.x;
    int v = (i < n) ? g_deg[i] : 0;
#pragma unroll
    for (int off = 16; off > 0; off >>= 1)
        v += __shfl_xor_sync(0xFFFFFFFFu, v, off);
    int lane = threadIdx.x & 31, wid = threadIdx.x >> 5;
    if (lane == 0) wsum[wid] = v;
    __syncthreads();
    if (wid == 0) {
        int s = wsum[lane];
#pragma unroll
        for (int off = 16; off > 0; off >>= 1)
            s += __shfl_xor_sync(0xFFFFFFFFu, s, off);
        if (lane == 0) g_bsum[blockIdx.x] = s;
    }
}

__global__ void k_scan_wr(int n, int e, int nb) {
    __shared__ int wsum[32];
    __shared__ int sboff;
    int lane = threadIdx.x & 31, wid = threadIdx.x >> 5;

    if (wid == 0) {
        int acc = 0;
        for (int j = lane; j < nb; j += 32)
            acc += (j < blockIdx.x) ? g_bsum[j] : 0;
#pragma unroll
        for (int off = 16; off > 0; off >>= 1)
            acc += __shfl_xor_sync(0xFFFFFFFFu, acc, off);
        if (lane == 0) sboff = acc;
    }

    int i = blockIdx.x * 1024 + threadIdx.x;
    int v = (i < n) ? g_deg[i] : 0;
    int x = v;
#pragma unroll
    for (int off = 1; off < 32; off <<= 1) {
        int y = __shfl_up_sync(0xFFFFFFFFu, x, off);
        if (lane >= off) x += y;
    }
    if (lane == 31) wsum[wid] = x;
    __syncthreads();
    if (wid == 0) {
        int w = wsum[lane];
#pragma unroll
        for (int off = 1; off < 32; off <<= 1) {
            int y = __shfl_up_sync(0xFFFFFFFFu, w, off);
            if (lane >= off) w += y;
        }
        wsum[lane] = w;
    }
    __syncthreads();
    int excl = x - v + ((wid > 0) ? wsum[wid - 1] : 0) + sboff;
    if (i < n) { g_rowptr[i] = excl; g_deg[i] = 0; }
    if (i == n) g_rowptr[n] = e;
}

// ---------------- scatter (rank-based, no atomics) ----------------
__global__ void k_scatter(const int* __restrict__ src, const int* __restrict__ dst, int e) {
    int i = blockIdx.x * blockDim.x + threadIdx.x;
    if (i >= e) return;
    int p = g_rowptr[dst[i]] + g_rank[i];
    g_csrsrc[p] = src[i];
}

// ---------------- attention layer 1: 4 lanes/node, prefetched ----------------
__global__ void k_attn1(int n) {
    int gt = blockIdx.x * blockDim.x + threadIdx.x;
    int node = gt >> 2;
    int sub = gt & 3;
    bool valid = (node < n);

    float4 cf0, cf1, cf2, cf3;
    int beg = 0, end = 0;
    if (valid) {
        cf0 = g_cf[node * 4 + 0];
        cf1 = g_cf[node * 4 + 1];
        cf2 = g_cf[node * 4 + 2];
        cf3 = g_cf[node * 4 + 3];
        beg = g_rowptr[node];
        end = g_rowptr[node + 1];
    }

    float4 ds0 = make_float4(0.f, 0.f, 0.f, 0.f);
    float4 ds1 = make_float4(0.f, 0.f, 0.f, 0.f);
    float4 ds2 = make_float4(0.f, 0.f, 0.f, 0.f);
    float4 ds3 = make_float4(0.f, 0.f, 0.f, 0.f);

    int i = beg + sub;
    float4 xs_c = make_float4(0.f, 0.f, 0.f, 0.f);
    if (i < end) xs_c = g_x4[g_csrsrc[i]];
    while (i < end) {
        int i2 = i + 4;
        float4 xs_n;
        if (i2 < end) xs_n = g_x4[g_csrsrc[i2]];   // prefetch next iteration
        float4 xs = xs_c;
        float w0 = __expf(cf0.w + cf0.x * xs.x + cf0.y * xs.y + cf0.z * xs.z);
        float w1 = __expf(cf1.w + cf1.x * xs.x + cf1.y * xs.y + cf1.z * xs.z);
        float w2 = __expf(cf2.w + cf2.x * xs.x + cf2.y * xs.y + cf2.z * xs.z);
        float w3 = __expf(cf3.w + cf3.x * xs.x + cf3.y * xs.y + cf3.z * xs.z);
        ds0.x += w0; ds0.y += w0 * xs.x; ds0.z += w0 * xs.y; ds0.w += w0 * xs.z;
        ds1.x += w1; ds1.y += w1 * xs.x; ds1.z += w1 * xs.y; ds1.w += w1 * xs.z;
        ds2.x += w2; ds2.y += w2 * xs.x; ds2.z += w2 * xs.y; ds2.w += w2 * xs.z;
        ds3.x += w3; ds3.y += w3 * xs.x; ds3.z += w3 * xs.y; ds3.w += w3 * xs.z;
        xs_c = xs_n;
        i = i2;
    }

#pragma unroll
    for (int off = 1; off <= 2; off <<= 1) {
        ds0.x += __shfl_xor_sync(0xFFFFFFFFu, ds0.x, off);
        ds0.y += __shfl_xor_sync(0xFFFFFFFFu, ds0.y, off);
        ds0.z += __shfl_xor_sync(0xFFFFFFFFu, ds0.z, off);
        ds0.w += __shfl_xor_sync(0xFFFFFFFFu, ds0.w, off);
        ds1.x += __shfl_xor_sync(0xFFFFFFFFu, ds1.x, off);
        ds1.y += __shfl_xor_sync(0xFFFFFFFFu, ds1.y, off);
        ds1.z += __shfl_xor_sync(0xFFFFFFFFu, ds1.z, off);
        ds1.w += __shfl_xor_sync(0xFFFFFFFFu, ds1.w, off);
        ds2.x += __shfl_xor_sync(0xFFFFFFFFu, ds2.x, off);
        ds2.y += __shfl_xor_sync(0xFFFFFFFFu, ds2.y, off);
        ds2.z += __shfl_xor_sync(0xFFFFFFFFu, ds2.z, off);
        ds2.w += __shfl_xor_sync(0xFFFFFFFFu, ds2.w, off);
        ds3.x += __shfl_xor_sync(0xFFFFFFFFu, ds3.x, off);
        ds3.y += __shfl_xor_sync(0xFFFFFFFFu, ds3.y, off);
        ds3.z += __shfl_xor_sync(0xFFFFFFFFu, ds3.z, off);
        ds3.w += __shfl_xor_sync(0xFFFFFFFFu, ds3.w, off);
    }

    if (valid) {
        float4 myds = (sub == 0) ? ds0 : (sub == 1) ? ds1 : (sub == 2) ? ds2 : ds3;
        g_ds[node * 4 + sub] = myds;
    }
}

// ---------------- layer 2 projection: 32 nodes/block, fused layer-1 epilogue ----------------
__global__ void __launch_bounds__(1024)
k_gemm2(const float* __restrict__ Wv1, const float* __restrict__ bv1,
        const float* __restrict__ Ws1, const float* __restrict__ bs1,
        const float* __restrict__ Wq, const float* __restrict__ bq,
        const float* __restrict__ Wk, const float* __restrict__ bk,
        const float* __restrict__ Wv, const float* __restrict__ bv,
        const float* __restrict__ Ws, const float* __restrict__ bs,
        int n) {
    __shared__ float  shH[32][64];
    __shared__ float  shW2[4][390];
    __shared__ float  shB2[4][6];
    __shared__ float  shWv[192], shBv[64], shWs[192], shBs[64];
    __shared__ float4 shDS[128];
    __shared__ float4 shX[32];
    int tid = threadIdx.x;
    int blk = blockIdx.x;

    for (int i = tid; i < 384 * 4; i += 1024) {
        int mm = i / 384, r = i % 384;
        const float* W = (mm == 0) ? Wq : (mm == 1) ? Wk : (mm == 2) ? Wv : Ws;
        shW2[mm][r] = W[r];
    }
    if (tid < 24) {
        int mm = tid / 6, cc = tid % 6;
        const float* b = (mm == 0) ? bq : (mm == 1) ? bk : (mm == 2) ? bv : bs;
        shB2[mm][cc] = b[cc];
    }
    if (tid < 192) { shWv[tid] = Wv1[tid]; shWs[tid] = Ws1[tid]; }
    else if (tid < 256) { shBv[tid - 192] = bv1[tid - 192]; shBs[tid - 192] = bs1[tid - 192]; }
    if (tid < 128) {
        int gidx = blk * 128 + tid;
        shDS[tid] = (gidx < n * 4) ? g_ds[gidx] : make_float4(0.f, 0.f, 0.f, 0.f);
    }
    if (tid < 32) {
        int node = blk * 32 + tid;
        shX[tid] = (node < n) ? g_x4[node] : make_float4(0.f, 0.f, 0.f, 0.f);
    }
    __syncthreads();

#pragma unroll
    for (int r = 0; r < 2; r++) {
        int idx = tid + r * 1024;
        int local = idx >> 6, c = idx & 63;
        float4 ds = shDS[local * 4 + (c >> 4)];
        float4 xt = shX[local];
        float num = shBv[c] * ds.x + shWv[c] * ds.y + shWv[64 + c] * ds.z + shWv[128 + c] * ds.w;
        float val = num / (ds.x + 1e-16f)
                  + shBs[c] + xt.x * shWs[c] + xt.y * shWs[64 + c] + xt.z * shWs[128 + c];
        shH[local][c] = fmaxf(val, 0.f);
    }
    __syncthreads();

    int w = tid >> 5;
    int lane = tid & 31;
    int node = blk * 32 + w;
    if (node >= n || lane >= 24) return;
    int mm = lane / 6, cc = lane % 6;
    float acc = shB2[mm][cc];
#pragma unroll
    for (int k = 0; k < 64; k++) acc += shH[w][k] * shW2[mm][k * 6 + cc];
    if (mm == 0)      g_qs[node * 16 + cc]      = acc * 0.4082482904638631f;
    else if (mm == 1) g_kvh[node * 16 + cc]     = __float2half(acc);
    else if (mm == 2) g_kvh[node * 16 + 6 + cc] = __float2half(acc);
    else              g_qs[node * 16 + 8 + cc]  = acc;
}

// ---------------- attention layer 2 + pooling + output (fused, ticket) ----------------
__global__ void k_attn2_pool(const int* __restrict__ batch, int n, float* __restrict__ out) {
    __shared__ float ssum[GG * 6];
    __shared__ float scnt[GG];
    __shared__ int   sflag[GG];
    __shared__ int   slast;
    int tid = threadIdx.x;
    for (int i = tid; i < GG * 6; i += blockDim.x) ssum[i] = 0.f;
    for (int i = tid; i < GG; i += blockDim.x) { scnt[i] = 0.f; sflag[i] = 0; }
    __syncthreads();

    int gt = blockIdx.x * blockDim.x + tid;
    int node = gt >> 2;
    int sub = gt & 3;
    bool valid = (node < n);

    float4 qa = make_float4(0.f, 0.f, 0.f, 0.f);
    float2 qb = make_float2(0.f, 0.f);
    int beg = 0, end = 0;
    if (valid) {
        qa = *reinterpret_cast<const float4*>(g_qs + node * 16);
        qb = *reinterpret_cast<const float2*>(g_qs + node * 16 + 4);
        beg = g_rowptr[node];
        end = g_rowptr[node + 1];
    }

    const uint4* kv = reinterpret_cast<const uint4*>(g_kvh);

    float den = 0.f;
    float a0 = 0.f, a1 = 0.f, a2 = 0.f, a3 = 0.f, a4 = 0.f, a5 = 0.f;

    int i = beg + sub;
    uint4 r0c = make_uint4(0, 0, 0, 0), r1c = make_uint4(0, 0, 0, 0);
    if (i < end) {
        int s = g_csrsrc[i];
        r0c = kv[s * 2 + 0];
        r1c = kv[s * 2 + 1];
    }
    while (i < end) {
        int i2 = i + 4;
        uint4 r0n, r1n;
        if (i2 < end) {                        // prefetch next iteration
            int s2 = g_csrsrc[i2];
            r0n = kv[s2 * 2 + 0];
            r1n = kv[s2 * 2 + 1];
        }
        float2 k01 = __half22float2(*reinterpret_cast<const __half2*>(&r0c.x));
        float2 k23 = __half22float2(*reinterpret_cast<const __half2*>(&r0c.y));
        float2 k45 = __half22float2(*reinterpret_cast<const __half2*>(&r0c.z));
        float2 v01 = __half22float2(*reinterpret_cast<const __half2*>(&r0c.w));
        float2 v23 = __half22float2(*reinterpret_cast<const __half2*>(&r1c.x));
        float2 v45 = __half22float2(*reinterpret_cast<const __half2*>(&r1c.y));
        float l = qa.x * k01.x + qa.y * k01.y + qa.z * k23.x + qa.w * k23.y
                + qb.x * k45.x + qb.y * k45.y;
        float w = __expf(l);
        den += w;
        a0 += w * v01.x; a1 += w * v01.y;
        a2 += w * v23.x; a3 += w * v23.y;
        a4 += w * v45.x; a5 += w * v45.y;
        r0c = r0n; r1c = r1n;
        i = i2;
    }

#pragma unroll
    for (int off = 1; off <= 2; off <<= 1) {
        den += __shfl_xor_sync(0xFFFFFFFFu, den, off);
        a0 += __shfl_xor_sync(0xFFFFFFFFu, a0, off);
        a1 += __shfl_xor_sync(0xFFFFFFFFu, a1, off);
        a2 += __shfl_xor_sync(0xFFFFFFFFu, a2, off);
        a3 += __shfl_xor_sync(0xFFFFFFFFu, a3, off);
        a4 += __shfl_xor_sync(0xFFFFFFFFu, a4, off);
        a5 += __shfl_xor_sync(0xFFFFFFFFu, a5, off);
    }

    if (valid && sub == 0) {
        float inv = 1.f / (den + 1e-16f);
        int g = __ldg(&batch[node]);
        const float* sp = g_qs + node * 16 + 8;
        atomicAdd(&ssum[g * 6 + 0], a0 * inv + sp[0]);
        atomicAdd(&ssum[g * 6 + 1], a1 * inv + sp[1]);
        atomicAdd(&ssum[g * 6 + 2], a2 * inv + sp[2]);
        atomicAdd(&ssum[g * 6 + 3], a3 * inv + sp[3]);
        atomicAdd(&ssum[g * 6 + 4], a4 * inv + sp[4]);
        atomicAdd(&ssum[g * 6 + 5], a5 * inv + sp[5]);
        atomicAdd(&scnt[g], 1.f);
        sflag[g] = 1;
    }
    __syncthreads();
    for (int g = tid; g < GG; g += blockDim.x) {
        if (sflag[g]) {
            atomicAdd(&g_cnt[g], scnt[g]);
#pragma unroll
            for (int c = 0; c < 6; c++)
                atomicAdd(&g_sums[g * 6 + c], ssum[g * 6 + c]);
        }
    }
    __syncthreads();
    if (tid == 0) {
        __threadfence();
        int t = atomicAdd(&g_ticket, 1);
        slast = (t == (int)gridDim.x - 1) ? 1 : 0;
    }
    __syncthreads();
    if (slast) {
        __threadfence();
        int g = tid;
        if (g < GG) {
            float cnt = fmaxf(g_cnt[g], 1.f);
            float p[6];
            float m = -INFINITY;
#pragma unroll
            for (int c = 0; c < 6; c++) { p[c] = g_sums[g * 6 + c] / cnt; m = fmaxf(m, p[c]); }
            float s = 0.f;
#pragma unroll
            for (int c = 0; c < 6; c++) s += expf(p[c] - m);
            float lse = m + logf(s);
#pragma unroll
            for (int c = 0; c < 6; c++) out[g * 6 + c] = p[c] - lse;
        }
        __syncthreads();
        // restore zero-state invariant for the next launch
        for (int i2 = tid; i2 < GG * 6; i2 += blockDim.x) g_sums[i2] = 0.f;
        for (int i2 = tid; i2 < GG; i2 += blockDim.x) g_cnt[i2] = 0.f;
        if (tid == 0) g_ticket = 0;
    }
}

// ---------------- launch ----------------
extern "C" void kernel_launch(void* const* d_in, const int* in_sizes, int n_in,
                              void* d_out, int out_size) {
    const float* x    = (const float*)d_in[0];
    const int*   ei   = (const int*)  d_in[1];
    const int*   batch= (const int*)  d_in[2];
    const float* Wq1  = (const float*)d_in[3];
    const float* bq1  = (const float*)d_in[4];
    const float* Wk1  = (const float*)d_in[5];
    const float* bk1  = (const float*)d_in[6];
    const float* Wv1  = (const float*)d_in[7];
    const float* bv1  = (const float*)d_in[8];
    const float* Ws1  = (const float*)d_in[9];
    const float* bs1  = (const float*)d_in[10];
    const float* Wq2  = (const float*)d_in[11];
    const float* bq2  = (const float*)d_in[12];
    const float* Wk2  = (const float*)d_in[13];
    const float* bk2  = (const float*)d_in[14];
    const float* Wv2  = (const float*)d_in[15];
    const float* bv2  = (const float*)d_in[16];
    const float* Ws2  = (const float*)d_in[17];
    const float* bs2  = (const float*)d_in[18];
    float* out = (float*)d_out;

    int N = in_sizes[0] / 3;
    int E = in_sizes[1] / 2;
    const int* src = ei;
    const int* dst = ei + E;

    const int B = 256;
    int NB = (N + 1024) / 1024;

    k_prep_hist<<<(E + B - 1) / B, B>>>(x, dst, Wq1, bq1, Wk1, bk1, N, E);
    k_scan_blk<<<NB, 1024>>>(N);
    k_scan_wr<<<NB, 1024>>>(N, E, NB);
    k_scatter<<<(E + B - 1) / B, B>>>(src, dst, E);
    k_attn1<<<(N * 4 + B - 1) / B, B>>>(N);
    k_gemm2<<<(N + 31) / 32, 1024>>>(Wv1, bv1, Ws1, bs1,
                                     Wq2, bq2, Wk2, bk2, Wv2, bv2, Ws2, bs2, N);
    k_attn2_pool<<<(N * 4 + B - 1) / B, B>>>(batch, N, out);
}